// round 1
// baseline (speedup 1.0000x reference)
#include <cuda_runtime.h>

#define BDIM   2
#define NSEQ   2048
#define DMODEL 1024
#define NHEADS 16
#define DKH    64
#define TD     3072   // 3*DMODEL

// Scratch (static device globals: allocation-free rule)
__device__ float g_qkv[(size_t)BDIM * NSEQ * TD];      // 48 MB
__device__ float g_ctx[(size_t)BDIM * NSEQ * DMODEL];  // 16 MB

// ---------------------------------------------------------------------------
// C[M,Nc] = A[M,K] @ B[K,Nc] + bias[Nc]
// 64x64 tile, BK=16, 256 threads, 4x4 micro-tile per thread.
// ---------------------------------------------------------------------------
__global__ __launch_bounds__(256) void gemm_bias_kernel(
    const float* __restrict__ A, const float* __restrict__ Bm,
    const float* __restrict__ bias, float* __restrict__ C,
    int M, int Nc, int K)
{
    __shared__ float As[16][68];   // As[k][m]  (A tile transposed), padded
    __shared__ float Bs[16][64];   // Bs[k][n]

    const int tid = threadIdx.x;
    const int tx = tid & 15, ty = tid >> 4;
    const int bm = blockIdx.y * 64;
    const int bn = blockIdx.x * 64;

    const int arow = tid >> 2;          // 0..63
    const int acol = (tid & 3) * 4;     // 0,4,8,12
    const int brow = tid >> 4;          // 0..15
    const int bcol = (tid & 15) * 4;    // 0..60

    const float* Aptr = A + (size_t)(bm + arow) * K + acol;
    const float* Bptr = Bm + (size_t)brow * Nc + bn + bcol;

    float acc[4][4] = {};

    for (int k0 = 0; k0 < K; k0 += 16) {
        float4 av = *(const float4*)(Aptr + k0);
        As[acol + 0][arow] = av.x;
        As[acol + 1][arow] = av.y;
        As[acol + 2][arow] = av.z;
        As[acol + 3][arow] = av.w;
        *(float4*)&Bs[brow][bcol] = *(const float4*)(Bptr + (size_t)k0 * Nc);
        __syncthreads();

        #pragma unroll
        for (int k = 0; k < 16; ++k) {
            float4 a4 = *(const float4*)&As[k][ty * 4];
            float4 b4 = *(const float4*)&Bs[k][tx * 4];
            float a[4] = {a4.x, a4.y, a4.z, a4.w};
            float b[4] = {b4.x, b4.y, b4.z, b4.w};
            #pragma unroll
            for (int i = 0; i < 4; ++i)
                #pragma unroll
                for (int j = 0; j < 4; ++j)
                    acc[i][j] += a[i] * b[j];
        }
        __syncthreads();
    }

    float4 bs4 = *(const float4*)&bias[bn + tx * 4];
    float bb[4] = {bs4.x, bs4.y, bs4.z, bs4.w};
    #pragma unroll
    for (int i = 0; i < 4; ++i) {
        int r = bm + ty * 4 + i;
        float4 o;
        o.x = acc[i][0] + bb[0];
        o.y = acc[i][1] + bb[1];
        o.z = acc[i][2] + bb[2];
        o.w = acc[i][3] + bb[3];
        *(float4*)&C[(size_t)r * Nc + bn + tx * 4] = o;
    }
}

// ---------------------------------------------------------------------------
// Attention: two-pass softmax per 64-query tile.
// grid = (NSEQ/64, NHEADS*BDIM), 256 threads (16x16), 4x4 micro-tiles.
// Pass A: exact row max / sumexp streaming over key tiles.
// Pass B: recompute scores -> normalized probs -> context (P@V) + column sums.
// ---------------------------------------------------------------------------
__global__ __launch_bounds__(256) void attn_kernel(float* __restrict__ attn_mean)
{
    extern __shared__ float sm[];
    float* Qs = sm;                 // [64][68]  Qs[d*68 + r] (pre-scaled by 1/8)
    float* Ks = Qs + 64 * 68;       // [64][68]  Ks[d*68 + c]
    float* Vs = Ks + 64 * 68;       // [64][68]  Vs[c*68 + d]
    float* Ps = Vs + 64 * 68;       // [64][72]  Ps[key*72 + row]
    float* Cr = Ps + 64 * 72;       // [16][64]  column-sum staging

    const int tid = threadIdx.x;
    const int tx = tid & 15, ty = tid >> 4;
    const int h = blockIdx.y >> 1;
    const int b = blockIdx.y & 1;
    const int q0 = blockIdx.x * 64;

    const float* base = g_qkv + (size_t)b * NSEQ * TD + h * (3 * DKH);

    // Load Q tile transposed, fold in softmax scale 1/sqrt(64)=0.125
    for (int idx = tid; idx < 64 * 64; idx += 256) {
        int r = idx >> 6, d = idx & 63;
        Qs[d * 68 + r] = base[(size_t)(q0 + r) * TD + d] * 0.125f;
    }

    float m[4], l[4];
    #pragma unroll
    for (int i = 0; i < 4; ++i) { m[i] = -1e30f; l[i] = 0.f; }

    // ---------------- PASS A: row max + sumexp ----------------
    for (int kt = 0; kt < NSEQ; kt += 64) {
        __syncthreads();
        for (int idx = tid; idx < 64 * 64; idx += 256) {
            int c = idx >> 6, d = idx & 63;
            Ks[d * 68 + c] = base[(size_t)(kt + c) * TD + DKH + d];
        }
        __syncthreads();

        float s[4][4] = {};
        #pragma unroll 8
        for (int d = 0; d < 64; ++d) {
            float4 a4 = *(const float4*)&Qs[d * 68 + ty * 4];
            float4 b4 = *(const float4*)&Ks[d * 68 + tx * 4];
            float a[4] = {a4.x, a4.y, a4.z, a4.w};
            float bq[4] = {b4.x, b4.y, b4.z, b4.w};
            #pragma unroll
            for (int i = 0; i < 4; ++i)
                #pragma unroll
                for (int j = 0; j < 4; ++j)
                    s[i][j] += a[i] * bq[j];
        }

        #pragma unroll
        for (int i = 0; i < 4; ++i) {
            float tm = fmaxf(fmaxf(s[i][0], s[i][1]), fmaxf(s[i][2], s[i][3]));
            #pragma unroll
            for (int off = 8; off; off >>= 1)
                tm = fmaxf(tm, __shfl_xor_sync(0xffffffffu, tm, off, 16));
            float nm = fmaxf(m[i], tm);
            float ps = __expf(s[i][0] - nm) + __expf(s[i][1] - nm)
                     + __expf(s[i][2] - nm) + __expf(s[i][3] - nm);
            #pragma unroll
            for (int off = 8; off; off >>= 1)
                ps += __shfl_xor_sync(0xffffffffu, ps, off, 16);
            l[i] = l[i] * __expf(m[i] - nm) + ps;
            m[i] = nm;
        }
    }

    float rl[4];
    #pragma unroll
    for (int i = 0; i < 4; ++i) rl[i] = 1.0f / l[i];

    float ctx[4][4] = {};

    // ---------------- PASS B: probs, context, column sums ----------------
    for (int kt = 0; kt < NSEQ; kt += 64) {
        __syncthreads();
        for (int idx = tid; idx < 64 * 64; idx += 256) {
            int c = idx >> 6, d = idx & 63;
            Ks[d * 68 + c] = base[(size_t)(kt + c) * TD + DKH + d];
            Vs[c * 68 + d] = base[(size_t)(kt + c) * TD + 2 * DKH + d];
        }
        __syncthreads();

        float s[4][4] = {};
        #pragma unroll 8
        for (int d = 0; d < 64; ++d) {
            float4 a4 = *(const float4*)&Qs[d * 68 + ty * 4];
            float4 b4 = *(const float4*)&Ks[d * 68 + tx * 4];
            float a[4] = {a4.x, a4.y, a4.z, a4.w};
            float bq[4] = {b4.x, b4.y, b4.z, b4.w};
            #pragma unroll
            for (int i = 0; i < 4; ++i)
                #pragma unroll
                for (int j = 0; j < 4; ++j)
                    s[i][j] += a[i] * bq[j];
        }

        float colp[4] = {0.f, 0.f, 0.f, 0.f};
        #pragma unroll
        for (int i = 0; i < 4; ++i) {
            #pragma unroll
            for (int j = 0; j < 4; ++j) {
                float p = __expf(s[i][j] - m[i]) * rl[i];
                Ps[(tx * 4 + j) * 72 + ty * 4 + i] = p;
                colp[j] += p;
            }
        }
        *(float4*)&Cr[ty * 64 + tx * 4] =
            make_float4(colp[0], colp[1], colp[2], colp[3]);
        __syncthreads();

        if (tid < 64) {
            float tot = 0.f;
            #pragma unroll
            for (int r = 0; r < 16; ++r) tot += Cr[r * 64 + tid];
            atomicAdd(&attn_mean[b * NSEQ + kt + tid],
                      tot * (1.0f / (NHEADS * (float)NSEQ)));
        }

        #pragma unroll 4
        for (int j = 0; j < 64; ++j) {
            float4 v4 = *(const float4*)&Vs[j * 68 + tx * 4];
            float vv[4] = {v4.x, v4.y, v4.z, v4.w};
            float a0 = Ps[j * 72 + ty * 4 + 0];
            float a1 = Ps[j * 72 + ty * 4 + 1];
            float a2 = Ps[j * 72 + ty * 4 + 2];
            float a3 = Ps[j * 72 + ty * 4 + 3];
            #pragma unroll
            for (int jj = 0; jj < 4; ++jj) {
                ctx[0][jj] += a0 * vv[jj];
                ctx[1][jj] += a1 * vv[jj];
                ctx[2][jj] += a2 * vv[jj];
                ctx[3][jj] += a3 * vv[jj];
            }
        }
    }

    // context layout: (B, N, H, dk) flattened to (B, N, D)
    #pragma unroll
    for (int i = 0; i < 4; ++i) {
        int r = q0 + ty * 4 + i;
        float* dst = &g_ctx[((size_t)(b * NSEQ + r)) * DMODEL + h * DKH + tx * 4];
        *(float4*)dst = make_float4(ctx[i][0], ctx[i][1], ctx[i][2], ctx[i][3]);
    }
}

// ---------------------------------------------------------------------------
extern "C" void kernel_launch(void* const* d_in, const int* in_sizes, int n_in,
                              void* d_out, int out_size)
{
    const float* x     = (const float*)d_in[0];
    const float* w_qkv = (const float*)d_in[1];
    const float* b_qkv = (const float*)d_in[2];
    const float* w_out = (const float*)d_in[3];
    const float* b_out = (const float*)d_in[4];
    float* out = (float*)d_out;

    float *qkv_ptr = nullptr, *ctx_ptr = nullptr;
    cudaGetSymbolAddress((void**)&qkv_ptr, g_qkv);
    cudaGetSymbolAddress((void**)&ctx_ptr, g_ctx);

    const int M = BDIM * NSEQ;                 // 4096
    float* attn_mean = out + (size_t)M * DMODEL;  // second output region

    // attn_mean accumulated via atomics -> zero it
    cudaMemsetAsync(attn_mean, 0, (size_t)BDIM * NSEQ * sizeof(float));

    // QKV projection: (4096,1024)@(1024,3072)+b
    gemm_bias_kernel<<<dim3(TD / 64, M / 64), 256>>>(
        x, w_qkv, b_qkv, qkv_ptr, M, TD, DMODEL);

    // attention
    const size_t attn_smem = (size_t)(3 * 64 * 68 + 64 * 72 + 16 * 64) * sizeof(float);
    cudaFuncSetAttribute(attn_kernel,
                         cudaFuncAttributeMaxDynamicSharedMemorySize,
                         (int)attn_smem);
    attn_kernel<<<dim3(NSEQ / 64, NHEADS * BDIM), 256, attn_smem>>>(attn_mean);

    // output projection: (4096,1024)@(1024,1024)+b
    gemm_bias_kernel<<<dim3(DMODEL / 64, M / 64), 256>>>(
        ctx_ptr, w_out, b_out, out, M, DMODEL, DMODEL);
}

// round 3
// speedup vs baseline: 1.2839x; 1.2839x over previous
#include <cuda_runtime.h>
#include <cuda_bf16.h>
#include <cstdint>

#define BDIM   2
#define NSEQ   2048
#define DMODEL 1024
#define NHEADS 16
#define DKH    64
#define TD     3072   // 3*DMODEL

// ---------------------------------------------------------------------------
// Scratch (static device globals: allocation-free rule)
// ---------------------------------------------------------------------------
__device__ float g_qkv[(size_t)BDIM * NSEQ * TD];      // 48 MB fp32
__device__ float g_ctx[(size_t)BDIM * NSEQ * DMODEL];  // 16 MB fp32
__device__ __nv_bfloat16 g_xhi[(size_t)BDIM * NSEQ * DMODEL];
__device__ __nv_bfloat16 g_xlo[(size_t)BDIM * NSEQ * DMODEL];
__device__ __nv_bfloat16 g_ctxhi[(size_t)BDIM * NSEQ * DMODEL];
__device__ __nv_bfloat16 g_ctxlo[(size_t)BDIM * NSEQ * DMODEL];
__device__ __nv_bfloat16 g_wqkvT_hi[(size_t)TD * DMODEL];   // [N=3072][K=1024]
__device__ __nv_bfloat16 g_wqkvT_lo[(size_t)TD * DMODEL];
__device__ __nv_bfloat16 g_woutT_hi[(size_t)DMODEL * DMODEL];
__device__ __nv_bfloat16 g_woutT_lo[(size_t)DMODEL * DMODEL];

// ---------------------------------------------------------------------------
// PTX helpers (baseline ISA only: compiles under compute_103)
// ---------------------------------------------------------------------------
__device__ __forceinline__ uint32_t smem_to_u32(const void* p) {
    uint32_t a;
    asm("{ .reg .u64 t; cvta.to.shared.u64 t, %1; cvt.u32.u64 %0, t; }"
        : "=r"(a) : "l"(p));
    return a;
}
__device__ __forceinline__ void cp16(uint32_t s, const void* g) {
    asm volatile("cp.async.ca.shared.global [%0], [%1], 16;" :: "r"(s), "l"(g));
}
__device__ __forceinline__ void cp_commit() {
    asm volatile("cp.async.commit_group;");
}
template <int N> __device__ __forceinline__ void cp_wait() {
    asm volatile("cp.async.wait_group %0;" :: "n"(N));
}
__device__ __forceinline__ void ldsm_x4(uint32_t* r, uint32_t addr) {
    asm volatile("ldmatrix.sync.aligned.m8n8.x4.shared.b16 {%0,%1,%2,%3}, [%4];"
        : "=r"(r[0]), "=r"(r[1]), "=r"(r[2]), "=r"(r[3]) : "r"(addr));
}
__device__ __forceinline__ void mma_bf16(float* d, const uint32_t* a,
                                         uint32_t b0, uint32_t b1) {
    asm volatile(
        "mma.sync.aligned.m16n8k16.row.col.f32.bf16.bf16.f32 "
        "{%0,%1,%2,%3}, {%4,%5,%6,%7}, {%8,%9}, {%0,%1,%2,%3};"
        : "+f"(d[0]), "+f"(d[1]), "+f"(d[2]), "+f"(d[3])
        : "r"(a[0]), "r"(a[1]), "r"(a[2]), "r"(a[3]), "r"(b0), "r"(b1));
}

// ---------------------------------------------------------------------------
// Split fp32 -> (hi, lo) bf16, elementwise (row-major preserved)
// ---------------------------------------------------------------------------
__global__ __launch_bounds__(256) void split_kernel(
    const float* __restrict__ src, __nv_bfloat16* __restrict__ hi,
    __nv_bfloat16* __restrict__ lo, int n2)  // n2 = n/2
{
    for (int i = blockIdx.x * blockDim.x + threadIdx.x; i < n2;
         i += gridDim.x * blockDim.x) {
        float2 v = ((const float2*)src)[i];
        __nv_bfloat16 hx = __float2bfloat16(v.x);
        __nv_bfloat16 hy = __float2bfloat16(v.y);
        __nv_bfloat162 h; h.x = hx; h.y = hy;
        __nv_bfloat162 l;
        l.x = __float2bfloat16(v.x - __bfloat162float(hx));
        l.y = __float2bfloat16(v.y - __bfloat162float(hy));
        ((__nv_bfloat162*)hi)[i] = h;
        ((__nv_bfloat162*)lo)[i] = l;
    }
}

// ---------------------------------------------------------------------------
// Split + transpose: src [K][N] fp32 -> hiT/loT [N][K] bf16
// ---------------------------------------------------------------------------
__global__ __launch_bounds__(256) void split_transpose_kernel(
    const float* __restrict__ src, __nv_bfloat16* __restrict__ hiT,
    __nv_bfloat16* __restrict__ loT, int K, int N)
{
    __shared__ float tile[32][33];
    const int tx = threadIdx.x, ty = threadIdx.y;   // (32, 8)
    const int n0 = blockIdx.x * 32, k0 = blockIdx.y * 32;

    #pragma unroll
    for (int i = 0; i < 4; ++i)
        tile[ty + i * 8][tx] = src[(size_t)(k0 + ty + i * 8) * N + n0 + tx];
    __syncthreads();

    #pragma unroll
    for (int i = 0; i < 4; ++i) {
        int n = n0 + ty + i * 8;
        float v = tile[tx][ty + i * 8];
        __nv_bfloat16 h = __float2bfloat16(v);
        hiT[(size_t)n * K + k0 + tx] = h;
        loT[(size_t)n * K + k0 + tx] = __float2bfloat16(v - __bfloat162float(h));
    }
}

// ---------------------------------------------------------------------------
// bf16 split GEMM: C[M,Nc] = A[M,K] @ B[K,Nc] + bias
// A given as hi/lo bf16 row-major [M][K]; B given as hi/lo bf16 TRANSPOSED
// [Nc][K]. 3-term split: hh + lh + hl, fp32 accumulate.
// CTA 128x128, BK=32, 256 threads (8 warps, warp tile 32x64), cp.async 2-stage.
// ---------------------------------------------------------------------------
#define AHI_OFF 0
#define ALO_OFF 10240
#define BHI_OFF 20480
#define BLO_OFF 38912
#define STAGE_SZ 57344
static constexpr size_t GEMM_SMEM = 2 * STAGE_SZ;  // 114688

__global__ __launch_bounds__(256) void gemm_mma_kernel(
    const __nv_bfloat16* __restrict__ Ahi, const __nv_bfloat16* __restrict__ Alo,
    const __nv_bfloat16* __restrict__ BThi, const __nv_bfloat16* __restrict__ BTlo,
    const float* __restrict__ bias, float* __restrict__ C,
    int M, int Nc, int K)
{
    extern __shared__ char smc[];
    const uint32_t sbase = smem_to_u32(smc);
    const int tid = threadIdx.x;
    const int lane = tid & 31, wid = tid >> 5;
    const int wm = (wid & 3) * 32;       // warp m offset in tile
    const int wn = (wid >> 2) * 64;      // warp n offset in tile
    const int bm = blockIdx.y * 128, bn = blockIdx.x * 128;

    // loader mapping: 2 threads per row, 2x 16B chunks each
    const int lrow = tid >> 1;
    const int lc   = (tid & 1) * 2;

    const __nv_bfloat16* gAh = Ahi + (size_t)(bm + lrow) * K + lc * 8;
    const __nv_bfloat16* gAl = Alo + (size_t)(bm + lrow) * K + lc * 8;
    const __nv_bfloat16* gBh = BThi + (size_t)(bn + lrow) * K + lc * 8;
    const __nv_bfloat16* gBl = BTlo + (size_t)(bn + lrow) * K + lc * 8;

    const uint32_t sA = lrow * 80 + lc * 16;
    const uint32_t sB = lrow * 144 + lc * 16;

    auto load_stage = [&](int k0, int buf) {
        uint32_t st = sbase + buf * STAGE_SZ;
        cp16(st + AHI_OFF + sA,      gAh + k0);
        cp16(st + AHI_OFF + sA + 16, gAh + k0 + 8);
        cp16(st + ALO_OFF + sA,      gAl + k0);
        cp16(st + ALO_OFF + sA + 16, gAl + k0 + 8);
        cp16(st + BHI_OFF + sB,      gBh + k0);
        cp16(st + BHI_OFF + sB + 16, gBh + k0 + 8);
        cp16(st + BLO_OFF + sB,      gBl + k0);
        cp16(st + BLO_OFF + sB + 16, gBl + k0 + 8);
    };

    float acc[2][8][4];
    #pragma unroll
    for (int a = 0; a < 2; ++a)
        #pragma unroll
        for (int b = 0; b < 8; ++b)
            #pragma unroll
            for (int c = 0; c < 4; ++c) acc[a][b][c] = 0.f;

    const int arow = wm + (lane & 15);
    const int brow = wn + (lane & 15);
    const int klb  = ((lane >> 4) << 3) * 2;  // byte offset of lane's k half

    const int nit = K / 32;
    load_stage(0, 0);
    cp_commit();

    for (int i = 0; i < nit; ++i) {
        const int cur = i & 1;
        if (i + 1 < nit) { load_stage((i + 1) * 32, cur ^ 1); cp_commit(); }
        if (i + 1 < nit) cp_wait<1>(); else cp_wait<0>();
        __syncthreads();

        const uint32_t st = sbase + cur * STAGE_SZ;
        #pragma unroll
        for (int ks = 0; ks < 2; ++ks) {
            const uint32_t kb = ks * 32 + klb;
            uint32_t ah[2][4], al[2][4], bh[4][4], bl[4][4];
            #pragma unroll
            for (int mt = 0; mt < 2; ++mt) {
                ldsm_x4(ah[mt], st + AHI_OFF + (arow + mt * 16) * 80 + kb);
                ldsm_x4(al[mt], st + ALO_OFF + (arow + mt * 16) * 80 + kb);
            }
            #pragma unroll
            for (int nt = 0; nt < 4; ++nt) {
                ldsm_x4(bh[nt], st + BHI_OFF + (brow + nt * 16) * 144 + kb);
                ldsm_x4(bl[nt], st + BLO_OFF + (brow + nt * 16) * 144 + kb);
            }
            #pragma unroll
            for (int mt = 0; mt < 2; ++mt)
                #pragma unroll
                for (int j = 0; j < 8; ++j) {
                    const int nt = j >> 1, o = j & 1;
                    uint32_t b0h = bh[nt][o], b1h = bh[nt][o + 2];
                    uint32_t b0l = bl[nt][o], b1l = bl[nt][o + 2];
                    mma_bf16(acc[mt][j], ah[mt], b0h, b1h);
                    mma_bf16(acc[mt][j], al[mt], b0h, b1h);
                    mma_bf16(acc[mt][j], ah[mt], b0l, b1l);
                }
        }
        __syncthreads();
    }

    // epilogue
    const int g = lane >> 2, tq = lane & 3;
    #pragma unroll
    for (int mt = 0; mt < 2; ++mt) {
        const int r0 = bm + wm + mt * 16 + g;
        #pragma unroll
        for (int j = 0; j < 8; ++j) {
            const int col = bn + wn + j * 8 + tq * 2;
            const float b0 = bias[col], b1 = bias[col + 1];
            float2 v0 = make_float2(acc[mt][j][0] + b0, acc[mt][j][1] + b1);
            float2 v1 = make_float2(acc[mt][j][2] + b0, acc[mt][j][3] + b1);
            *(float2*)&C[(size_t)r0 * Nc + col] = v0;
            *(float2*)&C[(size_t)(r0 + 8) * Nc + col] = v1;
        }
    }
}

// ---------------------------------------------------------------------------
// Attention: two-pass softmax per 64-query tile (R1 version, fp32 SIMT).
// ---------------------------------------------------------------------------
__global__ __launch_bounds__(256) void attn_kernel(float* __restrict__ attn_mean)
{
    extern __shared__ float sm[];
    float* Qs = sm;                 // [64][68]
    float* Ks = Qs + 64 * 68;       // [64][68]
    float* Vs = Ks + 64 * 68;       // [64][68]
    float* Ps = Vs + 64 * 68;       // [64][72]
    float* Cr = Ps + 64 * 72;       // [16][64]

    const int tid = threadIdx.x;
    const int tx = tid & 15, ty = tid >> 4;
    const int h = blockIdx.y >> 1;
    const int b = blockIdx.y & 1;
    const int q0 = blockIdx.x * 64;

    const float* base = g_qkv + (size_t)b * NSEQ * TD + h * (3 * DKH);

    for (int idx = tid; idx < 64 * 64; idx += 256) {
        int r = idx >> 6, d = idx & 63;
        Qs[d * 68 + r] = base[(size_t)(q0 + r) * TD + d] * 0.125f;
    }

    float m[4], l[4];
    #pragma unroll
    for (int i = 0; i < 4; ++i) { m[i] = -1e30f; l[i] = 0.f; }

    for (int kt = 0; kt < NSEQ; kt += 64) {
        __syncthreads();
        for (int idx = tid; idx < 64 * 64; idx += 256) {
            int c = idx >> 6, d = idx & 63;
            Ks[d * 68 + c] = base[(size_t)(kt + c) * TD + DKH + d];
        }
        __syncthreads();

        float s[4][4] = {};
        #pragma unroll 8
        for (int d = 0; d < 64; ++d) {
            float4 a4 = *(const float4*)&Qs[d * 68 + ty * 4];
            float4 b4 = *(const float4*)&Ks[d * 68 + tx * 4];
            float a[4] = {a4.x, a4.y, a4.z, a4.w};
            float bq[4] = {b4.x, b4.y, b4.z, b4.w};
            #pragma unroll
            for (int i = 0; i < 4; ++i)
                #pragma unroll
                for (int j = 0; j < 4; ++j)
                    s[i][j] += a[i] * bq[j];
        }

        #pragma unroll
        for (int i = 0; i < 4; ++i) {
            float tm = fmaxf(fmaxf(s[i][0], s[i][1]), fmaxf(s[i][2], s[i][3]));
            #pragma unroll
            for (int off = 8; off; off >>= 1)
                tm = fmaxf(tm, __shfl_xor_sync(0xffffffffu, tm, off, 16));
            float nm = fmaxf(m[i], tm);
            float ps = __expf(s[i][0] - nm) + __expf(s[i][1] - nm)
                     + __expf(s[i][2] - nm) + __expf(s[i][3] - nm);
            #pragma unroll
            for (int off = 8; off; off >>= 1)
                ps += __shfl_xor_sync(0xffffffffu, ps, off, 16);
            l[i] = l[i] * __expf(m[i] - nm) + ps;
            m[i] = nm;
        }
    }

    float rl[4];
    #pragma unroll
    for (int i = 0; i < 4; ++i) rl[i] = 1.0f / l[i];

    float ctx[4][4] = {};

    for (int kt = 0; kt < NSEQ; kt += 64) {
        __syncthreads();
        for (int idx = tid; idx < 64 * 64; idx += 256) {
            int c = idx >> 6, d = idx & 63;
            Ks[d * 68 + c] = base[(size_t)(kt + c) * TD + DKH + d];
            Vs[c * 68 + d] = base[(size_t)(kt + c) * TD + 2 * DKH + d];
        }
        __syncthreads();

        float s[4][4] = {};
        #pragma unroll 8
        for (int d = 0; d < 64; ++d) {
            float4 a4 = *(const float4*)&Qs[d * 68 + ty * 4];
            float4 b4 = *(const float4*)&Ks[d * 68 + tx * 4];
            float a[4] = {a4.x, a4.y, a4.z, a4.w};
            float bq[4] = {b4.x, b4.y, b4.z, b4.w};
            #pragma unroll
            for (int i = 0; i < 4; ++i)
                #pragma unroll
                for (int j = 0; j < 4; ++j)
                    s[i][j] += a[i] * bq[j];
        }

        float colp[4] = {0.f, 0.f, 0.f, 0.f};
        #pragma unroll
        for (int i = 0; i < 4; ++i) {
            #pragma unroll
            for (int j = 0; j < 4; ++j) {
                float p = __expf(s[i][j] - m[i]) * rl[i];
                Ps[(tx * 4 + j) * 72 + ty * 4 + i] = p;
                colp[j] += p;
            }
        }
        *(float4*)&Cr[ty * 64 + tx * 4] =
            make_float4(colp[0], colp[1], colp[2], colp[3]);
        __syncthreads();

        if (tid < 64) {
            float tot = 0.f;
            #pragma unroll
            for (int r = 0; r < 16; ++r) tot += Cr[r * 64 + tid];
            atomicAdd(&attn_mean[b * NSEQ + kt + tid],
                      tot * (1.0f / (NHEADS * (float)NSEQ)));
        }

        #pragma unroll 4
        for (int j = 0; j < 64; ++j) {
            float4 v4 = *(const float4*)&Vs[j * 68 + tx * 4];
            float vv[4] = {v4.x, v4.y, v4.z, v4.w};
            float a0 = Ps[j * 72 + ty * 4 + 0];
            float a1 = Ps[j * 72 + ty * 4 + 1];
            float a2 = Ps[j * 72 + ty * 4 + 2];
            float a3 = Ps[j * 72 + ty * 4 + 3];
            #pragma unroll
            for (int jj = 0; jj < 4; ++jj) {
                ctx[0][jj] += a0 * vv[jj];
                ctx[1][jj] += a1 * vv[jj];
                ctx[2][jj] += a2 * vv[jj];
                ctx[3][jj] += a3 * vv[jj];
            }
        }
    }

    #pragma unroll
    for (int i = 0; i < 4; ++i) {
        int r = q0 + ty * 4 + i;
        float* dst = &g_ctx[((size_t)(b * NSEQ + r)) * DMODEL + h * DKH + tx * 4];
        *(float4*)dst = make_float4(ctx[i][0], ctx[i][1], ctx[i][2], ctx[i][3]);
    }
}

// ---------------------------------------------------------------------------
extern "C" void kernel_launch(void* const* d_in, const int* in_sizes, int n_in,
                              void* d_out, int out_size)
{
    const float* x     = (const float*)d_in[0];
    const float* w_qkv = (const float*)d_in[1];
    const float* b_qkv = (const float*)d_in[2];
    const float* w_out = (const float*)d_in[3];
    const float* b_out = (const float*)d_in[4];
    float* out = (float*)d_out;

    float *qkv_ptr = nullptr, *ctx_ptr = nullptr;
    cudaGetSymbolAddress((void**)&qkv_ptr, g_qkv);
    cudaGetSymbolAddress((void**)&ctx_ptr, g_ctx);
    __nv_bfloat16 *xhi, *xlo, *ctxhi, *ctxlo, *wqh, *wql, *woh, *wol;
    cudaGetSymbolAddress((void**)&xhi, g_xhi);
    cudaGetSymbolAddress((void**)&xlo, g_xlo);
    cudaGetSymbolAddress((void**)&ctxhi, g_ctxhi);
    cudaGetSymbolAddress((void**)&ctxlo, g_ctxlo);
    cudaGetSymbolAddress((void**)&wqh, g_wqkvT_hi);
    cudaGetSymbolAddress((void**)&wql, g_wqkvT_lo);
    cudaGetSymbolAddress((void**)&woh, g_woutT_hi);
    cudaGetSymbolAddress((void**)&wol, g_woutT_lo);

    const int M = BDIM * NSEQ;                    // 4096
    float* attn_mean = out + (size_t)M * DMODEL;  // second output region

    cudaMemsetAsync(attn_mean, 0, (size_t)BDIM * NSEQ * sizeof(float));

    // split inputs
    split_kernel<<<1024, 256>>>(x, xhi, xlo, M * DMODEL / 2);
    split_transpose_kernel<<<dim3(TD / 32, DMODEL / 32), dim3(32, 8)>>>(
        w_qkv, wqh, wql, DMODEL, TD);
    split_transpose_kernel<<<dim3(DMODEL / 32, DMODEL / 32), dim3(32, 8)>>>(
        w_out, woh, wol, DMODEL, DMODEL);

    cudaFuncSetAttribute(gemm_mma_kernel,
                         cudaFuncAttributeMaxDynamicSharedMemorySize,
                         (int)GEMM_SMEM);

    // QKV projection: (4096,1024)@(1024,3072)+b
    gemm_mma_kernel<<<dim3(TD / 128, M / 128), 256, GEMM_SMEM>>>(
        xhi, xlo, wqh, wql, b_qkv, qkv_ptr, M, TD, DMODEL);

    // attention
    const size_t attn_smem = (size_t)(3 * 64 * 68 + 64 * 72 + 16 * 64) * sizeof(float);
    cudaFuncSetAttribute(attn_kernel,
                         cudaFuncAttributeMaxDynamicSharedMemorySize,
                         (int)attn_smem);
    attn_kernel<<<dim3(NSEQ / 64, NHEADS * BDIM), 256, attn_smem>>>(attn_mean);

    // split context, then output projection
    split_kernel<<<1024, 256>>>(ctx_ptr, ctxhi, ctxlo, M * DMODEL / 2);
    gemm_mma_kernel<<<dim3(DMODEL / 128, M / 128), 256, GEMM_SMEM>>>(
        ctxhi, ctxlo, woh, wol, b_out, out, M, DMODEL, DMODEL);
}

// round 4
// speedup vs baseline: 2.6446x; 2.0598x over previous
#include <cuda_runtime.h>
#include <cuda_bf16.h>
#include <cstdint>

#define BDIM   2
#define NSEQ   2048
#define DMODEL 1024
#define NHEADS 16
#define DKH    64
#define TD     3072   // 3*DMODEL

// ---------------------------------------------------------------------------
// Scratch (static device globals: allocation-free rule)
// ---------------------------------------------------------------------------
__device__ __nv_bfloat16 g_qkvhi[(size_t)BDIM * NSEQ * TD];     // 24 MB
__device__ __nv_bfloat16 g_qkvlo[(size_t)BDIM * NSEQ * TD];     // 24 MB
__device__ __nv_bfloat16 g_xhi[(size_t)BDIM * NSEQ * DMODEL];
__device__ __nv_bfloat16 g_xlo[(size_t)BDIM * NSEQ * DMODEL];
__device__ __nv_bfloat16 g_ctxhi[(size_t)BDIM * NSEQ * DMODEL];
__device__ __nv_bfloat16 g_ctxlo[(size_t)BDIM * NSEQ * DMODEL];
__device__ __nv_bfloat16 g_wqkvT_hi[(size_t)TD * DMODEL];   // [N=3072][K=1024]
__device__ __nv_bfloat16 g_wqkvT_lo[(size_t)TD * DMODEL];
__device__ __nv_bfloat16 g_woutT_hi[(size_t)DMODEL * DMODEL];
__device__ __nv_bfloat16 g_woutT_lo[(size_t)DMODEL * DMODEL];

// ---------------------------------------------------------------------------
// PTX helpers (baseline ISA only: compiles under compute_103)
// ---------------------------------------------------------------------------
__device__ __forceinline__ uint32_t smem_to_u32(const void* p) {
    uint32_t a;
    asm("{ .reg .u64 t; cvta.to.shared.u64 t, %1; cvt.u32.u64 %0, t; }"
        : "=r"(a) : "l"(p));
    return a;
}
__device__ __forceinline__ void cp16(uint32_t s, const void* g) {
    asm volatile("cp.async.ca.shared.global [%0], [%1], 16;" :: "r"(s), "l"(g));
}
__device__ __forceinline__ void cp_commit() {
    asm volatile("cp.async.commit_group;");
}
template <int N> __device__ __forceinline__ void cp_wait() {
    asm volatile("cp.async.wait_group %0;" :: "n"(N));
}
__device__ __forceinline__ void ldsm_x4(uint32_t* r, uint32_t addr) {
    asm volatile("ldmatrix.sync.aligned.m8n8.x4.shared.b16 {%0,%1,%2,%3}, [%4];"
        : "=r"(r[0]), "=r"(r[1]), "=r"(r[2]), "=r"(r[3]) : "r"(addr));
}
__device__ __forceinline__ void ldsm_x4_t(uint32_t* r, uint32_t addr) {
    asm volatile("ldmatrix.sync.aligned.m8n8.x4.trans.shared.b16 {%0,%1,%2,%3}, [%4];"
        : "=r"(r[0]), "=r"(r[1]), "=r"(r[2]), "=r"(r[3]) : "r"(addr));
}
__device__ __forceinline__ void mma_bf16(float* d, const uint32_t* a,
                                         uint32_t b0, uint32_t b1) {
    asm volatile(
        "mma.sync.aligned.m16n8k16.row.col.f32.bf16.bf16.f32 "
        "{%0,%1,%2,%3}, {%4,%5,%6,%7}, {%8,%9}, {%0,%1,%2,%3};"
        : "+f"(d[0]), "+f"(d[1]), "+f"(d[2]), "+f"(d[3])
        : "r"(a[0]), "r"(a[1]), "r"(a[2]), "r"(a[3]), "r"(b0), "r"(b1));
}
__device__ __forceinline__ float ex2(float x) {
    float y; asm("ex2.approx.f32 %0, %1;" : "=f"(y) : "f"(x)); return y;
}
__device__ __forceinline__ void pack_hl(float x, float y,
                                        uint32_t& hp, uint32_t& lp) {
    __nv_bfloat162 hh = __floats2bfloat162_rn(x, y);
    __nv_bfloat162 ll = __floats2bfloat162_rn(
        x - __bfloat162float(hh.x), y - __bfloat162float(hh.y));
    hp = *(uint32_t*)&hh; lp = *(uint32_t*)&ll;
}
__device__ __forceinline__ void split_store2(__nv_bfloat16* hi, __nv_bfloat16* lo,
                                             size_t idx, float x, float y) {
    __nv_bfloat162 hh = __floats2bfloat162_rn(x, y);
    __nv_bfloat162 ll = __floats2bfloat162_rn(
        x - __bfloat162float(hh.x), y - __bfloat162float(hh.y));
    *(uint32_t*)(hi + idx) = *(uint32_t*)&hh;
    *(uint32_t*)(lo + idx) = *(uint32_t*)&ll;
}

// ---------------------------------------------------------------------------
// Split fp32 -> (hi, lo) bf16, elementwise
// ---------------------------------------------------------------------------
__global__ __launch_bounds__(256) void split_kernel(
    const float* __restrict__ src, __nv_bfloat16* __restrict__ hi,
    __nv_bfloat16* __restrict__ lo, int n2)
{
    for (int i = blockIdx.x * blockDim.x + threadIdx.x; i < n2;
         i += gridDim.x * blockDim.x) {
        float2 v = ((const float2*)src)[i];
        split_store2(hi, lo, (size_t)i * 2, v.x, v.y);
    }
}

// ---------------------------------------------------------------------------
// Split + transpose: src [K][N] fp32 -> hiT/loT [N][K] bf16
// ---------------------------------------------------------------------------
__global__ __launch_bounds__(256) void split_transpose_kernel(
    const float* __restrict__ src, __nv_bfloat16* __restrict__ hiT,
    __nv_bfloat16* __restrict__ loT, int K, int N)
{
    __shared__ float tile[32][33];
    const int tx = threadIdx.x, ty = threadIdx.y;   // (32, 8)
    const int n0 = blockIdx.x * 32, k0 = blockIdx.y * 32;

    #pragma unroll
    for (int i = 0; i < 4; ++i)
        tile[ty + i * 8][tx] = src[(size_t)(k0 + ty + i * 8) * N + n0 + tx];
    __syncthreads();

    #pragma unroll
    for (int i = 0; i < 4; ++i) {
        int n = n0 + ty + i * 8;
        float v = tile[tx][ty + i * 8];
        __nv_bfloat16 h = __float2bfloat16(v);
        hiT[(size_t)n * K + k0 + tx] = h;
        loT[(size_t)n * K + k0 + tx] = __float2bfloat16(v - __bfloat162float(h));
    }
}

// ---------------------------------------------------------------------------
// bf16 split GEMM: C = A @ B + bias; A hi/lo [M][K]; B hi/lo transposed [Nc][K]
// Output either fp32 C, or split bf16 (Chi, Clo).
// ---------------------------------------------------------------------------
#define AHI_OFF 0
#define ALO_OFF 10240
#define BHI_OFF 20480
#define BLO_OFF 38912
#define STAGE_SZ 57344
static constexpr size_t GEMM_SMEM = 2 * STAGE_SZ;  // 114688

__global__ __launch_bounds__(256) void gemm_mma_kernel(
    const __nv_bfloat16* __restrict__ Ahi, const __nv_bfloat16* __restrict__ Alo,
    const __nv_bfloat16* __restrict__ BThi, const __nv_bfloat16* __restrict__ BTlo,
    const float* __restrict__ bias, float* __restrict__ C,
    __nv_bfloat16* __restrict__ Chi, __nv_bfloat16* __restrict__ Clo,
    int M, int Nc, int K)
{
    extern __shared__ char smc[];
    const uint32_t sbase = smem_to_u32(smc);
    const int tid = threadIdx.x;
    const int lane = tid & 31, wid = tid >> 5;
    const int wm = (wid & 3) * 32;
    const int wn = (wid >> 2) * 64;
    const int bm = blockIdx.y * 128, bn = blockIdx.x * 128;

    const int lrow = tid >> 1;
    const int lc   = (tid & 1) * 2;

    const __nv_bfloat16* gAh = Ahi + (size_t)(bm + lrow) * K + lc * 8;
    const __nv_bfloat16* gAl = Alo + (size_t)(bm + lrow) * K + lc * 8;
    const __nv_bfloat16* gBh = BThi + (size_t)(bn + lrow) * K + lc * 8;
    const __nv_bfloat16* gBl = BTlo + (size_t)(bn + lrow) * K + lc * 8;

    const uint32_t sA = lrow * 80 + lc * 16;
    const uint32_t sB = lrow * 144 + lc * 16;

    auto load_stage = [&](int k0, int buf) {
        uint32_t st = sbase + buf * STAGE_SZ;
        cp16(st + AHI_OFF + sA,      gAh + k0);
        cp16(st + AHI_OFF + sA + 16, gAh + k0 + 8);
        cp16(st + ALO_OFF + sA,      gAl + k0);
        cp16(st + ALO_OFF + sA + 16, gAl + k0 + 8);
        cp16(st + BHI_OFF + sB,      gBh + k0);
        cp16(st + BHI_OFF + sB + 16, gBh + k0 + 8);
        cp16(st + BLO_OFF + sB,      gBl + k0);
        cp16(st + BLO_OFF + sB + 16, gBl + k0 + 8);
    };

    float acc[2][8][4];
    #pragma unroll
    for (int a = 0; a < 2; ++a)
        #pragma unroll
        for (int b = 0; b < 8; ++b)
            #pragma unroll
            for (int c = 0; c < 4; ++c) acc[a][b][c] = 0.f;

    const int arow = wm + (lane & 15);
    const int brow = wn + (lane & 15);
    const int klb  = (lane >> 4) * 16;

    const int nit = K / 32;
    load_stage(0, 0);
    cp_commit();

    for (int i = 0; i < nit; ++i) {
        const int cur = i & 1;
        if (i + 1 < nit) { load_stage((i + 1) * 32, cur ^ 1); cp_commit(); }
        if (i + 1 < nit) cp_wait<1>(); else cp_wait<0>();
        __syncthreads();

        const uint32_t st = sbase + cur * STAGE_SZ;
        #pragma unroll
        for (int ks = 0; ks < 2; ++ks) {
            const uint32_t kb = ks * 32 + klb;
            uint32_t ah[2][4], al[2][4], bh[4][4], bl[4][4];
            #pragma unroll
            for (int mt = 0; mt < 2; ++mt) {
                ldsm_x4(ah[mt], st + AHI_OFF + (arow + mt * 16) * 80 + kb);
                ldsm_x4(al[mt], st + ALO_OFF + (arow + mt * 16) * 80 + kb);
            }
            #pragma unroll
            for (int nt = 0; nt < 4; ++nt) {
                ldsm_x4(bh[nt], st + BHI_OFF + (brow + nt * 16) * 144 + kb);
                ldsm_x4(bl[nt], st + BLO_OFF + (brow + nt * 16) * 144 + kb);
            }
            #pragma unroll
            for (int mt = 0; mt < 2; ++mt)
                #pragma unroll
                for (int j = 0; j < 8; ++j) {
                    const int nt = j >> 1, o = j & 1;
                    uint32_t b0h = bh[nt][o], b1h = bh[nt][o + 2];
                    uint32_t b0l = bl[nt][o], b1l = bl[nt][o + 2];
                    mma_bf16(acc[mt][j], ah[mt], b0h, b1h);
                    mma_bf16(acc[mt][j], al[mt], b0h, b1h);
                    mma_bf16(acc[mt][j], ah[mt], b0l, b1l);
                }
        }
        __syncthreads();
    }

    // epilogue
    const int g = lane >> 2, tq = lane & 3;
    #pragma unroll
    for (int mt = 0; mt < 2; ++mt) {
        const int r0 = bm + wm + mt * 16 + g;
        #pragma unroll
        for (int j = 0; j < 8; ++j) {
            const int col = bn + wn + j * 8 + tq * 2;
            const float b0 = bias[col], b1 = bias[col + 1];
            float v00 = acc[mt][j][0] + b0, v01 = acc[mt][j][1] + b1;
            float v10 = acc[mt][j][2] + b0, v11 = acc[mt][j][3] + b1;
            if (C) {
                *(float2*)&C[(size_t)r0 * Nc + col] = make_float2(v00, v01);
                *(float2*)&C[(size_t)(r0 + 8) * Nc + col] = make_float2(v10, v11);
            } else {
                split_store2(Chi, Clo, (size_t)r0 * Nc + col, v00, v01);
                split_store2(Chi, Clo, (size_t)(r0 + 8) * Nc + col, v10, v11);
            }
        }
    }
}

// ---------------------------------------------------------------------------
// MMA attention: 128 queries per CTA, 64-key tiles, two-pass softmax.
// smem: Q hi/lo [128][72bf16-pad144B]; 2 stages of K/V hi/lo [64][pad144B]; Cw.
// ---------------------------------------------------------------------------
#define ATT_QHI   0
#define ATT_QLO   18432
#define ATT_STG   36864
#define ATT_STAGE 36864
#define ATT_KHI   0
#define ATT_KLO   9216
#define ATT_VHI   18432
#define ATT_VLO   27648
#define ATT_CW    110592
#define ATT_SMEM  112640

__global__ __launch_bounds__(256) void attn_mma_kernel(float* __restrict__ attn_mean)
{
    extern __shared__ char smc[];
    const uint32_t sb = smem_to_u32(smc);
    float* Cw = (float*)(smc + ATT_CW);
    const int tid = threadIdx.x, lane = tid & 31, wid = tid >> 5;
    const int g = lane >> 2, tg = lane & 3;
    const int h = blockIdx.y >> 1, b = blockIdx.y & 1;
    const int q0 = blockIdx.x * 128;
    const float CEXP = 0.18033688f;  // 0.125 * log2(e)
    const float MSCALE = 1.0f / (NHEADS * (float)NSEQ);

    // ---- loaders (cp.async) ----
    auto loadQ = [&]() {
        #pragma unroll
        for (int i = 0; i < 4; ++i) {
            int c = i * 256 + tid; int r = c >> 3, ch = c & 7;
            size_t go = ((size_t)(b * NSEQ + q0 + r)) * TD + h * 192 + ch * 8;
            cp16(sb + ATT_QHI + r * 144 + ch * 16, g_qkvhi + go);
            cp16(sb + ATT_QLO + r * 144 + ch * 16, g_qkvlo + go);
        }
    };
    auto loadK = [&](int kt, int s) {
        uint32_t st = sb + ATT_STG + s * ATT_STAGE;
        #pragma unroll
        for (int i = 0; i < 2; ++i) {
            int c = i * 256 + tid; int r = c >> 3, ch = c & 7;
            size_t go = ((size_t)(b * NSEQ + kt * 64 + r)) * TD + h * 192 + 64 + ch * 8;
            cp16(st + ATT_KHI + r * 144 + ch * 16, g_qkvhi + go);
            cp16(st + ATT_KLO + r * 144 + ch * 16, g_qkvlo + go);
        }
    };
    auto loadKV = [&](int kt, int s) {
        loadK(kt, s);
        uint32_t st = sb + ATT_STG + s * ATT_STAGE;
        #pragma unroll
        for (int i = 0; i < 2; ++i) {
            int c = i * 256 + tid; int r = c >> 3, ch = c & 7;
            size_t go = ((size_t)(b * NSEQ + kt * 64 + r)) * TD + h * 192 + 128 + ch * 8;
            cp16(st + ATT_VHI + r * 144 + ch * 16, g_qkvhi + go);
            cp16(st + ATT_VLO + r * 144 + ch * 16, g_qkvlo + go);
        }
    };

    const uint32_t klb  = (lane >> 4) * 16;
    const uint32_t arow = wid * 16 + (lane & 15);
    const uint32_t brow = lane & 15;

    auto computeS = [&](uint32_t stg, float (*acc)[4]) {
        #pragma unroll
        for (int ks = 0; ks < 4; ++ks) {
            const uint32_t kb = ks * 32 + klb;
            uint32_t ah[4], al[4];
            ldsm_x4(ah, sb + ATT_QHI + arow * 144 + kb);
            ldsm_x4(al, sb + ATT_QLO + arow * 144 + kb);
            #pragma unroll
            for (int nt = 0; nt < 4; ++nt) {
                uint32_t bh[4], bl[4];
                ldsm_x4(bh, stg + ATT_KHI + (brow + nt * 16) * 144 + kb);
                ldsm_x4(bl, stg + ATT_KLO + (brow + nt * 16) * 144 + kb);
                #pragma unroll
                for (int o = 0; o < 2; ++o) {
                    const int j = nt * 2 + o;
                    mma_bf16(acc[j], ah, bh[o], bh[o + 2]);
                    mma_bf16(acc[j], al, bh[o], bh[o + 2]);
                    mma_bf16(acc[j], ah, bl[o], bl[o + 2]);
                }
            }
        }
    };

    float m0 = -1e30f, m1 = -1e30f, l0 = 0.f, l1 = 0.f;

    // ================= PASS A =================
    loadQ(); loadK(0, 0); cp_commit();
    loadK(1, 1); cp_commit();

    for (int kt = 0; kt < 32; ++kt) {
        cp_wait<1>();
        __syncthreads();
        const uint32_t stg = sb + ATT_STG + (kt & 1) * ATT_STAGE;

        float acc[8][4];
        #pragma unroll
        for (int j = 0; j < 8; ++j)
            #pragma unroll
            for (int x = 0; x < 4; ++x) acc[j][x] = 0.f;
        computeS(stg, acc);

        float mx0 = -1e30f, mx1 = -1e30f;
        #pragma unroll
        for (int j = 0; j < 8; ++j) {
            mx0 = fmaxf(mx0, fmaxf(acc[j][0], acc[j][1]));
            mx1 = fmaxf(mx1, fmaxf(acc[j][2], acc[j][3]));
        }
        mx0 = fmaxf(mx0, __shfl_xor_sync(0xffffffffu, mx0, 1));
        mx0 = fmaxf(mx0, __shfl_xor_sync(0xffffffffu, mx0, 2));
        mx1 = fmaxf(mx1, __shfl_xor_sync(0xffffffffu, mx1, 1));
        mx1 = fmaxf(mx1, __shfl_xor_sync(0xffffffffu, mx1, 2));
        const float nm0 = fmaxf(m0, mx0), nm1 = fmaxf(m1, mx1);
        float s0 = 0.f, s1 = 0.f;
        #pragma unroll
        for (int j = 0; j < 8; ++j) {
            s0 += ex2((acc[j][0] - nm0) * CEXP) + ex2((acc[j][1] - nm0) * CEXP);
            s1 += ex2((acc[j][2] - nm1) * CEXP) + ex2((acc[j][3] - nm1) * CEXP);
        }
        s0 += __shfl_xor_sync(0xffffffffu, s0, 1);
        s0 += __shfl_xor_sync(0xffffffffu, s0, 2);
        s1 += __shfl_xor_sync(0xffffffffu, s1, 1);
        s1 += __shfl_xor_sync(0xffffffffu, s1, 2);
        l0 = l0 * ex2((m0 - nm0) * CEXP) + s0; m0 = nm0;
        l1 = l1 * ex2((m1 - nm1) * CEXP) + s1; m1 = nm1;

        __syncthreads();
        if (kt + 2 < 32) loadK(kt + 2, kt & 1);
        cp_commit();
    }

    const float rl0 = 1.0f / l0, rl1 = 1.0f / l1;
    float ctx[8][4];
    #pragma unroll
    for (int j = 0; j < 8; ++j)
        #pragma unroll
        for (int x = 0; x < 4; ++x) ctx[j][x] = 0.f;

    // ================= PASS B =================
    loadKV(0, 0); cp_commit();
    loadKV(1, 1); cp_commit();

    for (int kt = 0; kt < 32; ++kt) {
        cp_wait<1>();
        __syncthreads();
        const uint32_t stg = sb + ATT_STG + (kt & 1) * ATT_STAGE;

        float acc[8][4];
        #pragma unroll
        for (int j = 0; j < 8; ++j)
            #pragma unroll
            for (int x = 0; x < 4; ++x) acc[j][x] = 0.f;
        computeS(stg, acc);

        // normalized probabilities + column partial sums
        float cp[16];
        #pragma unroll
        for (int j = 0; j < 8; ++j) {
            float p0 = ex2((acc[j][0] - m0) * CEXP) * rl0;
            float p1 = ex2((acc[j][1] - m0) * CEXP) * rl0;
            float p2 = ex2((acc[j][2] - m1) * CEXP) * rl1;
            float p3 = ex2((acc[j][3] - m1) * CEXP) * rl1;
            acc[j][0] = p0; acc[j][1] = p1; acc[j][2] = p2; acc[j][3] = p3;
            cp[2 * j] = p0 + p2; cp[2 * j + 1] = p1 + p3;
        }
        #pragma unroll
        for (int j = 0; j < 16; ++j) {
            cp[j] += __shfl_xor_sync(0xffffffffu, cp[j], 4);
            cp[j] += __shfl_xor_sync(0xffffffffu, cp[j], 8);
            cp[j] += __shfl_xor_sync(0xffffffffu, cp[j], 16);
        }
        if (lane < 4) {
            #pragma unroll
            for (int j = 0; j < 8; ++j) {
                Cw[wid * 64 + j * 8 + lane * 2]     = cp[2 * j];
                Cw[wid * 64 + j * 8 + lane * 2 + 1] = cp[2 * j + 1];
            }
        }

        // P @ V with register-reuse a-fragments
        #pragma unroll
        for (int kc = 0; kc < 4; ++kc) {
            const int j0 = kc * 2, j1 = j0 + 1;
            uint32_t aph[4], apl[4];
            pack_hl(acc[j0][0], acc[j0][1], aph[0], apl[0]);
            pack_hl(acc[j0][2], acc[j0][3], aph[1], apl[1]);
            pack_hl(acc[j1][0], acc[j1][1], aph[2], apl[2]);
            pack_hl(acc[j1][2], acc[j1][3], aph[3], apl[3]);
            #pragma unroll
            for (int dkt = 0; dkt < 4; ++dkt) {
                const uint32_t off = (kc * 16 + (lane & 15)) * 144 + dkt * 32
                                   + (lane >> 4) * 16;
                uint32_t vh[4], vl[4];
                ldsm_x4_t(vh, stg + ATT_VHI + off);
                ldsm_x4_t(vl, stg + ATT_VLO + off);
                mma_bf16(ctx[dkt * 2], aph, vh[0], vh[1]);
                mma_bf16(ctx[dkt * 2], apl, vh[0], vh[1]);
                mma_bf16(ctx[dkt * 2], aph, vl[0], vl[1]);
                mma_bf16(ctx[dkt * 2 + 1], aph, vh[2], vh[3]);
                mma_bf16(ctx[dkt * 2 + 1], apl, vh[2], vh[3]);
                mma_bf16(ctx[dkt * 2 + 1], aph, vl[2], vl[3]);
            }
        }

        __syncthreads();
        if (tid < 64) {
            float tot = 0.f;
            #pragma unroll
            for (int w = 0; w < 8; ++w) tot += Cw[w * 64 + tid];
            atomicAdd(&attn_mean[b * NSEQ + kt * 64 + tid], tot * MSCALE);
        }
        if (kt + 2 < 32) loadKV(kt + 2, kt & 1);
        cp_commit();
    }

    // epilogue: write context hi/lo bf16 (B, N, H*dk layout)
    const int r0 = q0 + wid * 16 + g;
    #pragma unroll
    for (int nd = 0; nd < 8; ++nd) {
        const int col = h * 64 + nd * 8 + tg * 2;
        size_t i0 = ((size_t)(b * NSEQ + r0)) * DMODEL + col;
        split_store2(g_ctxhi, g_ctxlo, i0, ctx[nd][0], ctx[nd][1]);
        split_store2(g_ctxhi, g_ctxlo, i0 + 8 * DMODEL, ctx[nd][2], ctx[nd][3]);
    }
}

// ---------------------------------------------------------------------------
extern "C" void kernel_launch(void* const* d_in, const int* in_sizes, int n_in,
                              void* d_out, int out_size)
{
    const float* x     = (const float*)d_in[0];
    const float* w_qkv = (const float*)d_in[1];
    const float* b_qkv = (const float*)d_in[2];
    const float* w_out = (const float*)d_in[3];
    const float* b_out = (const float*)d_in[4];
    float* out = (float*)d_out;

    __nv_bfloat16 *qh, *ql, *xhi, *xlo, *ctxhi, *ctxlo, *wqh, *wql, *woh, *wol;
    cudaGetSymbolAddress((void**)&qh, g_qkvhi);
    cudaGetSymbolAddress((void**)&ql, g_qkvlo);
    cudaGetSymbolAddress((void**)&xhi, g_xhi);
    cudaGetSymbolAddress((void**)&xlo, g_xlo);
    cudaGetSymbolAddress((void**)&ctxhi, g_ctxhi);
    cudaGetSymbolAddress((void**)&ctxlo, g_ctxlo);
    cudaGetSymbolAddress((void**)&wqh, g_wqkvT_hi);
    cudaGetSymbolAddress((void**)&wql, g_wqkvT_lo);
    cudaGetSymbolAddress((void**)&woh, g_woutT_hi);
    cudaGetSymbolAddress((void**)&wol, g_woutT_lo);

    const int M = BDIM * NSEQ;                    // 4096
    float* attn_mean = out + (size_t)M * DMODEL;  // second output region

    cudaMemsetAsync(attn_mean, 0, (size_t)BDIM * NSEQ * sizeof(float));

    // prep: split inputs / weights
    split_kernel<<<1024, 256>>>(x, xhi, xlo, M * DMODEL / 2);
    split_transpose_kernel<<<dim3(TD / 32, DMODEL / 32), dim3(32, 8)>>>(
        w_qkv, wqh, wql, DMODEL, TD);
    split_transpose_kernel<<<dim3(DMODEL / 32, DMODEL / 32), dim3(32, 8)>>>(
        w_out, woh, wol, DMODEL, DMODEL);

    cudaFuncSetAttribute(gemm_mma_kernel,
                         cudaFuncAttributeMaxDynamicSharedMemorySize,
                         (int)GEMM_SMEM);
    cudaFuncSetAttribute(attn_mma_kernel,
                         cudaFuncAttributeMaxDynamicSharedMemorySize,
                         ATT_SMEM);

    // QKV projection -> split bf16 output
    gemm_mma_kernel<<<dim3(TD / 128, M / 128), 256, GEMM_SMEM>>>(
        xhi, xlo, wqh, wql, b_qkv, nullptr, qh, ql, M, TD, DMODEL);

    // attention (mma, two-pass)
    attn_mma_kernel<<<dim3(NSEQ / 128, NHEADS * BDIM), 256, ATT_SMEM>>>(attn_mean);

    // output projection -> fp32 final output
    gemm_mma_kernel<<<dim3(DMODEL / 128, M / 128), 256, GEMM_SMEM>>>(
        ctxhi, ctxlo, woh, wol, b_out, out, nullptr, nullptr, M, DMODEL, DMODEL);
}

// round 5
// speedup vs baseline: 4.1045x; 1.5520x over previous
#include <cuda_runtime.h>
#include <cuda_fp16.h>
#include <cstdint>

#define BDIM   2
#define NSEQ   2048
#define DMODEL 1024
#define NHEADS 16
#define DKH    64
#define TD     3072   // 3*DMODEL

// ---------------------------------------------------------------------------
// Scratch (static device globals: allocation-free rule)
// ---------------------------------------------------------------------------
__device__ __half g_qkvhi[(size_t)BDIM * NSEQ * TD];
__device__ __half g_qkvlo[(size_t)BDIM * NSEQ * TD];
__device__ __half g_xhi[(size_t)BDIM * NSEQ * DMODEL];
__device__ __half g_xlo[(size_t)BDIM * NSEQ * DMODEL];
__device__ __half g_ctxhi[(size_t)BDIM * NSEQ * DMODEL];
__device__ __half g_ctxlo[(size_t)BDIM * NSEQ * DMODEL];
__device__ __half g_wqkvT_h[(size_t)TD * DMODEL];   // [N=3072][K=1024] hi only
__device__ __half g_woutT_h[(size_t)DMODEL * DMODEL];

// ---------------------------------------------------------------------------
// PTX helpers (baseline ISA only: compiles under compute_103)
// ---------------------------------------------------------------------------
__device__ __forceinline__ uint32_t smem_to_u32(const void* p) {
    uint32_t a;
    asm("{ .reg .u64 t; cvta.to.shared.u64 t, %1; cvt.u32.u64 %0, t; }"
        : "=r"(a) : "l"(p));
    return a;
}
__device__ __forceinline__ void cp16(uint32_t s, const void* g) {
    asm volatile("cp.async.ca.shared.global [%0], [%1], 16;" :: "r"(s), "l"(g));
}
__device__ __forceinline__ void cp_commit() {
    asm volatile("cp.async.commit_group;");
}
template <int N> __device__ __forceinline__ void cp_wait() {
    asm volatile("cp.async.wait_group %0;" :: "n"(N));
}
__device__ __forceinline__ void ldsm_x4(uint32_t* r, uint32_t addr) {
    asm volatile("ldmatrix.sync.aligned.m8n8.x4.shared.b16 {%0,%1,%2,%3}, [%4];"
        : "=r"(r[0]), "=r"(r[1]), "=r"(r[2]), "=r"(r[3]) : "r"(addr));
}
__device__ __forceinline__ void ldsm_x4_t(uint32_t* r, uint32_t addr) {
    asm volatile("ldmatrix.sync.aligned.m8n8.x4.trans.shared.b16 {%0,%1,%2,%3}, [%4];"
        : "=r"(r[0]), "=r"(r[1]), "=r"(r[2]), "=r"(r[3]) : "r"(addr));
}
__device__ __forceinline__ void mma_f16(float* d, const uint32_t* a,
                                        uint32_t b0, uint32_t b1) {
    asm volatile(
        "mma.sync.aligned.m16n8k16.row.col.f32.f16.f16.f32 "
        "{%0,%1,%2,%3}, {%4,%5,%6,%7}, {%8,%9}, {%0,%1,%2,%3};"
        : "+f"(d[0]), "+f"(d[1]), "+f"(d[2]), "+f"(d[3])
        : "r"(a[0]), "r"(a[1]), "r"(a[2]), "r"(a[3]), "r"(b0), "r"(b1));
}
__device__ __forceinline__ float ex2(float x) {
    float y; asm("ex2.approx.f32 %0, %1;" : "=f"(y) : "f"(x)); return y;
}
__device__ __forceinline__ void pack_hl(float x, float y,
                                        uint32_t& hp, uint32_t& lp) {
    __half2 hh = __floats2half2_rn(x, y);
    __half2 ll = __floats2half2_rn(x - __half2float(__low2half(hh)),
                                   y - __half2float(__high2half(hh)));
    hp = *(uint32_t*)&hh; lp = *(uint32_t*)&ll;
}
__device__ __forceinline__ void split_store2(__half* hi, __half* lo,
                                             size_t idx, float x, float y) {
    uint32_t hp, lp;
    pack_hl(x, y, hp, lp);
    *(uint32_t*)(hi + idx) = hp;
    *(uint32_t*)(lo + idx) = lp;
}

// ---------------------------------------------------------------------------
// Split fp32 -> (hi, lo) fp16, elementwise
// ---------------------------------------------------------------------------
__global__ __launch_bounds__(256) void split_kernel(
    const float* __restrict__ src, __half* __restrict__ hi,
    __half* __restrict__ lo, int n2)
{
    for (int i = blockIdx.x * blockDim.x + threadIdx.x; i < n2;
         i += gridDim.x * blockDim.x) {
        float2 v = ((const float2*)src)[i];
        split_store2(hi, lo, (size_t)i * 2, v.x, v.y);
    }
}

// ---------------------------------------------------------------------------
// Transpose + fp16 cast: src [K][N] fp32 -> hiT [N][K] fp16 (hi only)
// ---------------------------------------------------------------------------
__global__ __launch_bounds__(256) void transpose_h_kernel(
    const float* __restrict__ src, __half* __restrict__ hiT, int K, int N)
{
    __shared__ float tile[32][33];
    const int tx = threadIdx.x, ty = threadIdx.y;   // (32, 8)
    const int n0 = blockIdx.x * 32, k0 = blockIdx.y * 32;

    #pragma unroll
    for (int i = 0; i < 4; ++i)
        tile[ty + i * 8][tx] = src[(size_t)(k0 + ty + i * 8) * N + n0 + tx];
    __syncthreads();

    #pragma unroll
    for (int i = 0; i < 4; ++i) {
        int n = n0 + ty + i * 8;
        hiT[(size_t)n * K + k0 + tx] = __float2half_rn(tile[tx][ty + i * 8]);
    }
}

// ---------------------------------------------------------------------------
// fp16 2-term split GEMM: C = A @ B + bias
// A = hi/lo fp16 [M][K]; B = hi fp16 transposed [Nc][K].
// CTA 128x128, BK=32, 256 threads, warp tile 32x64, cp.async 2-stage.
// ---------------------------------------------------------------------------
#define AHI_OFF 0
#define ALO_OFF 10240
#define BHI_OFF 20480
#define STAGE_SZ 30720
static constexpr size_t GEMM_SMEM = 2 * STAGE_SZ;  // 61440

__global__ __launch_bounds__(256, 2) void gemm_mma_kernel(
    const __half* __restrict__ Ahi, const __half* __restrict__ Alo,
    const __half* __restrict__ BTh,
    const float* __restrict__ bias, float* __restrict__ C,
    __half* __restrict__ Chi, __half* __restrict__ Clo,
    int M, int Nc, int K)
{
    extern __shared__ char smc[];
    const uint32_t sbase = smem_to_u32(smc);
    const int tid = threadIdx.x;
    const int lane = tid & 31, wid = tid >> 5;
    const int wm = (wid & 3) * 32;
    const int wn = (wid >> 2) * 64;
    const int bm = blockIdx.y * 128, bn = blockIdx.x * 128;

    const int lrow = tid >> 1;
    const int lc   = (tid & 1) * 2;

    const __half* gAh = Ahi + (size_t)(bm + lrow) * K + lc * 8;
    const __half* gAl = Alo + (size_t)(bm + lrow) * K + lc * 8;
    const __half* gBh = BTh + (size_t)(bn + lrow) * K + lc * 8;

    const uint32_t sRow = lrow * 80 + lc * 16;

    auto load_stage = [&](int k0, int buf) {
        uint32_t st = sbase + buf * STAGE_SZ;
        cp16(st + AHI_OFF + sRow,      gAh + k0);
        cp16(st + AHI_OFF + sRow + 16, gAh + k0 + 8);
        cp16(st + ALO_OFF + sRow,      gAl + k0);
        cp16(st + ALO_OFF + sRow + 16, gAl + k0 + 8);
        cp16(st + BHI_OFF + sRow,      gBh + k0);
        cp16(st + BHI_OFF + sRow + 16, gBh + k0 + 8);
    };

    float acc[2][8][4];
    #pragma unroll
    for (int a = 0; a < 2; ++a)
        #pragma unroll
        for (int b = 0; b < 8; ++b)
            #pragma unroll
            for (int c = 0; c < 4; ++c) acc[a][b][c] = 0.f;

    const int arow = wm + (lane & 15);
    const int brow = wn + (lane & 15);
    const int klb  = (lane >> 4) * 16;

    const int nit = K / 32;
    load_stage(0, 0);
    cp_commit();

    for (int i = 0; i < nit; ++i) {
        const int cur = i & 1;
        if (i + 1 < nit) { load_stage((i + 1) * 32, cur ^ 1); cp_commit(); }
        if (i + 1 < nit) cp_wait<1>(); else cp_wait<0>();
        __syncthreads();

        const uint32_t st = sbase + cur * STAGE_SZ;
        #pragma unroll
        for (int ks = 0; ks < 2; ++ks) {
            const uint32_t kb = ks * 32 + klb;
            uint32_t ah[2][4], al[2][4], bh[4][4];
            #pragma unroll
            for (int mt = 0; mt < 2; ++mt) {
                ldsm_x4(ah[mt], st + AHI_OFF + (arow + mt * 16) * 80 + kb);
                ldsm_x4(al[mt], st + ALO_OFF + (arow + mt * 16) * 80 + kb);
            }
            #pragma unroll
            for (int nt = 0; nt < 4; ++nt)
                ldsm_x4(bh[nt], st + BHI_OFF + (brow + nt * 16) * 80 + kb);

            // all hh first (16 independent mmas), then all lh
            #pragma unroll
            for (int mt = 0; mt < 2; ++mt)
                #pragma unroll
                for (int j = 0; j < 8; ++j)
                    mma_f16(acc[mt][j], ah[mt], bh[j >> 1][j & 1],
                            bh[j >> 1][(j & 1) + 2]);
            #pragma unroll
            for (int mt = 0; mt < 2; ++mt)
                #pragma unroll
                for (int j = 0; j < 8; ++j)
                    mma_f16(acc[mt][j], al[mt], bh[j >> 1][j & 1],
                            bh[j >> 1][(j & 1) + 2]);
        }
        __syncthreads();
    }

    // epilogue
    const int g = lane >> 2, tq = lane & 3;
    #pragma unroll
    for (int mt = 0; mt < 2; ++mt) {
        const int r0 = bm + wm + mt * 16 + g;
        #pragma unroll
        for (int j = 0; j < 8; ++j) {
            const int col = bn + wn + j * 8 + tq * 2;
            const float b0 = bias[col], b1 = bias[col + 1];
            float v00 = acc[mt][j][0] + b0, v01 = acc[mt][j][1] + b1;
            float v10 = acc[mt][j][2] + b0, v11 = acc[mt][j][3] + b1;
            if (C) {
                *(float2*)&C[(size_t)r0 * Nc + col] = make_float2(v00, v01);
                *(float2*)&C[(size_t)(r0 + 8) * Nc + col] = make_float2(v10, v11);
            } else {
                split_store2(Chi, Clo, (size_t)r0 * Nc + col, v00, v01);
                split_store2(Chi, Clo, (size_t)(r0 + 8) * Nc + col, v10, v11);
            }
        }
    }
}

// ---------------------------------------------------------------------------
// MMA attention: 128 queries per CTA, 64-key tiles, two-pass softmax.
// Q = hi/lo fp16; K,V = hi fp16 only.
// ---------------------------------------------------------------------------
#define ATT_QHI   0
#define ATT_QLO   18432
#define ATT_STG   36864
#define ATT_STAGE 18432
#define ATT_VOF   9216
#define ATT_CW    73728
#define ATT_SMEM  75776

__global__ __launch_bounds__(256, 2) void attn_mma_kernel(float* __restrict__ attn_mean)
{
    extern __shared__ char smc[];
    const uint32_t sb = smem_to_u32(smc);
    float* Cw = (float*)(smc + ATT_CW);
    const int tid = threadIdx.x, lane = tid & 31, wid = tid >> 5;
    const int g = lane >> 2, tg = lane & 3;
    const int h = blockIdx.y >> 1, b = blockIdx.y & 1;
    const int q0 = blockIdx.x * 128;
    const float CEXP = 0.18033688f;  // 0.125 * log2(e)
    const float MSCALE = 1.0f / (NHEADS * (float)NSEQ);

    auto loadQ = [&]() {
        #pragma unroll
        for (int i = 0; i < 4; ++i) {
            int c = i * 256 + tid; int r = c >> 3, ch = c & 7;
            size_t go = ((size_t)(b * NSEQ + q0 + r)) * TD + h * 192 + ch * 8;
            cp16(sb + ATT_QHI + r * 144 + ch * 16, g_qkvhi + go);
            cp16(sb + ATT_QLO + r * 144 + ch * 16, g_qkvlo + go);
        }
    };
    auto loadK = [&](int kt, int s) {
        uint32_t st = sb + ATT_STG + s * ATT_STAGE;
        #pragma unroll
        for (int i = 0; i < 2; ++i) {
            int c = i * 256 + tid; int r = c >> 3, ch = c & 7;
            size_t go = ((size_t)(b * NSEQ + kt * 64 + r)) * TD + h * 192 + 64 + ch * 8;
            cp16(st + r * 144 + ch * 16, g_qkvhi + go);
        }
    };
    auto loadKV = [&](int kt, int s) {
        loadK(kt, s);
        uint32_t st = sb + ATT_STG + s * ATT_STAGE + ATT_VOF;
        #pragma unroll
        for (int i = 0; i < 2; ++i) {
            int c = i * 256 + tid; int r = c >> 3, ch = c & 7;
            size_t go = ((size_t)(b * NSEQ + kt * 64 + r)) * TD + h * 192 + 128 + ch * 8;
            cp16(st + r * 144 + ch * 16, g_qkvhi + go);
        }
    };

    const uint32_t klb  = (lane >> 4) * 16;
    const uint32_t arow = wid * 16 + (lane & 15);
    const uint32_t brow = lane & 15;

    auto computeS = [&](uint32_t stg, float (*acc)[4]) {
        #pragma unroll
        for (int ks = 0; ks < 4; ++ks) {
            const uint32_t kb = ks * 32 + klb;
            uint32_t ah[4], al[4], bh[4][4];
            ldsm_x4(ah, sb + ATT_QHI + arow * 144 + kb);
            ldsm_x4(al, sb + ATT_QLO + arow * 144 + kb);
            #pragma unroll
            for (int nt = 0; nt < 4; ++nt)
                ldsm_x4(bh[nt], stg + (brow + nt * 16) * 144 + kb);
            #pragma unroll
            for (int nt = 0; nt < 4; ++nt)
                #pragma unroll
                for (int o = 0; o < 2; ++o)
                    mma_f16(acc[nt * 2 + o], ah, bh[nt][o], bh[nt][o + 2]);
            #pragma unroll
            for (int nt = 0; nt < 4; ++nt)
                #pragma unroll
                for (int o = 0; o < 2; ++o)
                    mma_f16(acc[nt * 2 + o], al, bh[nt][o], bh[nt][o + 2]);
        }
    };

    float m0 = -1e30f, m1 = -1e30f, l0 = 0.f, l1 = 0.f;

    // ================= PASS A =================
    loadQ(); loadK(0, 0); cp_commit();
    loadK(1, 1); cp_commit();

    for (int kt = 0; kt < 32; ++kt) {
        cp_wait<1>();
        __syncthreads();
        const uint32_t stg = sb + ATT_STG + (kt & 1) * ATT_STAGE;

        float acc[8][4];
        #pragma unroll
        for (int j = 0; j < 8; ++j)
            #pragma unroll
            for (int x = 0; x < 4; ++x) acc[j][x] = 0.f;
        computeS(stg, acc);

        float mx0 = -1e30f, mx1 = -1e30f;
        #pragma unroll
        for (int j = 0; j < 8; ++j) {
            mx0 = fmaxf(mx0, fmaxf(acc[j][0], acc[j][1]));
            mx1 = fmaxf(mx1, fmaxf(acc[j][2], acc[j][3]));
        }
        mx0 = fmaxf(mx0, __shfl_xor_sync(0xffffffffu, mx0, 1));
        mx0 = fmaxf(mx0, __shfl_xor_sync(0xffffffffu, mx0, 2));
        mx1 = fmaxf(mx1, __shfl_xor_sync(0xffffffffu, mx1, 1));
        mx1 = fmaxf(mx1, __shfl_xor_sync(0xffffffffu, mx1, 2));
        const float nm0 = fmaxf(m0, mx0), nm1 = fmaxf(m1, mx1);
        float s0 = 0.f, s1 = 0.f;
        #pragma unroll
        for (int j = 0; j < 8; ++j) {
            s0 += ex2((acc[j][0] - nm0) * CEXP) + ex2((acc[j][1] - nm0) * CEXP);
            s1 += ex2((acc[j][2] - nm1) * CEXP) + ex2((acc[j][3] - nm1) * CEXP);
        }
        s0 += __shfl_xor_sync(0xffffffffu, s0, 1);
        s0 += __shfl_xor_sync(0xffffffffu, s0, 2);
        s1 += __shfl_xor_sync(0xffffffffu, s1, 1);
        s1 += __shfl_xor_sync(0xffffffffu, s1, 2);
        l0 = l0 * ex2((m0 - nm0) * CEXP) + s0; m0 = nm0;
        l1 = l1 * ex2((m1 - nm1) * CEXP) + s1; m1 = nm1;

        __syncthreads();
        if (kt + 2 < 32) loadK(kt + 2, kt & 1);
        cp_commit();
    }

    const float rl0 = 1.0f / l0, rl1 = 1.0f / l1;
    float ctx[8][4];
    #pragma unroll
    for (int j = 0; j < 8; ++j)
        #pragma unroll
        for (int x = 0; x < 4; ++x) ctx[j][x] = 0.f;

    // ================= PASS B =================
    loadKV(0, 0); cp_commit();
    loadKV(1, 1); cp_commit();

    for (int kt = 0; kt < 32; ++kt) {
        cp_wait<1>();
        __syncthreads();
        const uint32_t stg = sb + ATT_STG + (kt & 1) * ATT_STAGE;

        float acc[8][4];
        #pragma unroll
        for (int j = 0; j < 8; ++j)
            #pragma unroll
            for (int x = 0; x < 4; ++x) acc[j][x] = 0.f;
        computeS(stg, acc);

        // normalize + column sums (reduced per-j to limit live registers)
        #pragma unroll
        for (int j = 0; j < 8; ++j) {
            float p0 = ex2((acc[j][0] - m0) * CEXP) * rl0;
            float p1 = ex2((acc[j][1] - m0) * CEXP) * rl0;
            float p2 = ex2((acc[j][2] - m1) * CEXP) * rl1;
            float p3 = ex2((acc[j][3] - m1) * CEXP) * rl1;
            acc[j][0] = p0; acc[j][1] = p1; acc[j][2] = p2; acc[j][3] = p3;
            float c0 = p0 + p2, c1 = p1 + p3;
            c0 += __shfl_xor_sync(0xffffffffu, c0, 4);
            c0 += __shfl_xor_sync(0xffffffffu, c0, 8);
            c0 += __shfl_xor_sync(0xffffffffu, c0, 16);
            c1 += __shfl_xor_sync(0xffffffffu, c1, 4);
            c1 += __shfl_xor_sync(0xffffffffu, c1, 8);
            c1 += __shfl_xor_sync(0xffffffffu, c1, 16);
            if (lane < 4) {
                Cw[wid * 64 + j * 8 + lane * 2]     = c0;
                Cw[wid * 64 + j * 8 + lane * 2 + 1] = c1;
            }
        }

        // P @ V: P split hi/lo, V hi only
        #pragma unroll
        for (int kc = 0; kc < 4; ++kc) {
            const int j0 = kc * 2, j1 = j0 + 1;
            uint32_t aph[4], apl[4];
            pack_hl(acc[j0][0], acc[j0][1], aph[0], apl[0]);
            pack_hl(acc[j0][2], acc[j0][3], aph[1], apl[1]);
            pack_hl(acc[j1][0], acc[j1][1], aph[2], apl[2]);
            pack_hl(acc[j1][2], acc[j1][3], aph[3], apl[3]);
            #pragma unroll
            for (int dkt = 0; dkt < 4; ++dkt) {
                const uint32_t off = (kc * 16 + (lane & 15)) * 144 + dkt * 32
                                   + (lane >> 4) * 16;
                uint32_t vh[4];
                ldsm_x4_t(vh, stg + ATT_VOF + off);
                mma_f16(ctx[dkt * 2], aph, vh[0], vh[1]);
                mma_f16(ctx[dkt * 2], apl, vh[0], vh[1]);
                mma_f16(ctx[dkt * 2 + 1], aph, vh[2], vh[3]);
                mma_f16(ctx[dkt * 2 + 1], apl, vh[2], vh[3]);
            }
        }

        __syncthreads();
        if (tid < 64) {
            float tot = 0.f;
            #pragma unroll
            for (int w = 0; w < 8; ++w) tot += Cw[w * 64 + tid];
            atomicAdd(&attn_mean[b * NSEQ + kt * 64 + tid], tot * MSCALE);
        }
        if (kt + 2 < 32) loadKV(kt + 2, kt & 1);
        cp_commit();
    }

    // epilogue: write context hi/lo fp16 (B, N, H*dk layout)
    const int r0 = q0 + wid * 16 + g;
    #pragma unroll
    for (int nd = 0; nd < 8; ++nd) {
        const int col = h * 64 + nd * 8 + tg * 2;
        size_t i0 = ((size_t)(b * NSEQ + r0)) * DMODEL + col;
        split_store2(g_ctxhi, g_ctxlo, i0, ctx[nd][0], ctx[nd][1]);
        split_store2(g_ctxhi, g_ctxlo, i0 + 8 * DMODEL, ctx[nd][2], ctx[nd][3]);
    }
}

// ---------------------------------------------------------------------------
extern "C" void kernel_launch(void* const* d_in, const int* in_sizes, int n_in,
                              void* d_out, int out_size)
{
    const float* x     = (const float*)d_in[0];
    const float* w_qkv = (const float*)d_in[1];
    const float* b_qkv = (const float*)d_in[2];
    const float* w_out = (const float*)d_in[3];
    const float* b_out = (const float*)d_in[4];
    float* out = (float*)d_out;

    __half *qh, *ql, *xhi, *xlo, *ctxhi, *ctxlo, *wqh, *woh;
    cudaGetSymbolAddress((void**)&qh, g_qkvhi);
    cudaGetSymbolAddress((void**)&ql, g_qkvlo);
    cudaGetSymbolAddress((void**)&xhi, g_xhi);
    cudaGetSymbolAddress((void**)&xlo, g_xlo);
    cudaGetSymbolAddress((void**)&ctxhi, g_ctxhi);
    cudaGetSymbolAddress((void**)&ctxlo, g_ctxlo);
    cudaGetSymbolAddress((void**)&wqh, g_wqkvT_h);
    cudaGetSymbolAddress((void**)&woh, g_woutT_h);

    const int M = BDIM * NSEQ;                    // 4096
    float* attn_mean = out + (size_t)M * DMODEL;  // second output region

    cudaMemsetAsync(attn_mean, 0, (size_t)BDIM * NSEQ * sizeof(float));

    // prep: split input, cast+transpose weights (hi only)
    split_kernel<<<1024, 256>>>(x, xhi, xlo, M * DMODEL / 2);
    transpose_h_kernel<<<dim3(TD / 32, DMODEL / 32), dim3(32, 8)>>>(
        w_qkv, wqh, DMODEL, TD);
    transpose_h_kernel<<<dim3(DMODEL / 32, DMODEL / 32), dim3(32, 8)>>>(
        w_out, woh, DMODEL, DMODEL);

    cudaFuncSetAttribute(gemm_mma_kernel,
                         cudaFuncAttributeMaxDynamicSharedMemorySize,
                         (int)GEMM_SMEM);
    cudaFuncSetAttribute(attn_mma_kernel,
                         cudaFuncAttributeMaxDynamicSharedMemorySize,
                         ATT_SMEM);

    // QKV projection -> split fp16 output
    gemm_mma_kernel<<<dim3(TD / 128, M / 128), 256, GEMM_SMEM>>>(
        xhi, xlo, wqh, b_qkv, nullptr, qh, ql, M, TD, DMODEL);

    // attention (mma, two-pass)
    attn_mma_kernel<<<dim3(NSEQ / 128, NHEADS * BDIM), 256, ATT_SMEM>>>(attn_mean);

    // output projection -> fp32 final output
    gemm_mma_kernel<<<dim3(DMODEL / 128, M / 128), 256, GEMM_SMEM>>>(
        ctxhi, ctxlo, woh, b_out, out, nullptr, nullptr, M, DMODEL, DMODEL);
}

// round 6
// speedup vs baseline: 4.2972x; 1.0470x over previous
#include <cuda_runtime.h>
#include <cuda_fp16.h>
#include <cstdint>

#define BDIM   2
#define NSEQ   2048
#define DMODEL 1024
#define NHEADS 16
#define DKH    64
#define TD     3072   // 3*DMODEL

// ---------------------------------------------------------------------------
// Scratch (static device globals: allocation-free rule)
// ---------------------------------------------------------------------------
__device__ __half g_qkvhi[(size_t)BDIM * NSEQ * TD];
__device__ __half g_qkvlo[(size_t)BDIM * NSEQ * TD];
__device__ __half g_xhi[(size_t)BDIM * NSEQ * DMODEL];
__device__ __half g_xlo[(size_t)BDIM * NSEQ * DMODEL];
__device__ __half g_ctxhi[(size_t)BDIM * NSEQ * DMODEL];
__device__ __half g_ctxlo[(size_t)BDIM * NSEQ * DMODEL];
__device__ __half g_wqkvT_h[(size_t)TD * DMODEL];   // [N=3072][K=1024] hi only
__device__ __half g_woutT_h[(size_t)DMODEL * DMODEL];

// ---------------------------------------------------------------------------
// PTX helpers (baseline ISA only: compiles under compute_103)
// ---------------------------------------------------------------------------
__device__ __forceinline__ uint32_t smem_to_u32(const void* p) {
    uint32_t a;
    asm("{ .reg .u64 t; cvta.to.shared.u64 t, %1; cvt.u32.u64 %0, t; }"
        : "=r"(a) : "l"(p));
    return a;
}
__device__ __forceinline__ void cp16(uint32_t s, const void* g) {
    asm volatile("cp.async.ca.shared.global [%0], [%1], 16;" :: "r"(s), "l"(g));
}
__device__ __forceinline__ void cp_commit() {
    asm volatile("cp.async.commit_group;");
}
template <int N> __device__ __forceinline__ void cp_wait() {
    asm volatile("cp.async.wait_group %0;" :: "n"(N));
}
__device__ __forceinline__ void ldsm_x4(uint32_t* r, uint32_t addr) {
    asm volatile("ldmatrix.sync.aligned.m8n8.x4.shared.b16 {%0,%1,%2,%3}, [%4];"
        : "=r"(r[0]), "=r"(r[1]), "=r"(r[2]), "=r"(r[3]) : "r"(addr));
}
__device__ __forceinline__ void ldsm_x4_t(uint32_t* r, uint32_t addr) {
    asm volatile("ldmatrix.sync.aligned.m8n8.x4.trans.shared.b16 {%0,%1,%2,%3}, [%4];"
        : "=r"(r[0]), "=r"(r[1]), "=r"(r[2]), "=r"(r[3]) : "r"(addr));
}
__device__ __forceinline__ void mma_f16(float* d, const uint32_t* a,
                                        uint32_t b0, uint32_t b1) {
    asm volatile(
        "mma.sync.aligned.m16n8k16.row.col.f32.f16.f16.f32 "
        "{%0,%1,%2,%3}, {%4,%5,%6,%7}, {%8,%9}, {%0,%1,%2,%3};"
        : "+f"(d[0]), "+f"(d[1]), "+f"(d[2]), "+f"(d[3])
        : "r"(a[0]), "r"(a[1]), "r"(a[2]), "r"(a[3]), "r"(b0), "r"(b1));
}
__device__ __forceinline__ float ex2(float x) {
    float y; asm("ex2.approx.f32 %0, %1;" : "=f"(y) : "f"(x)); return y;
}
__device__ __forceinline__ float lg2(float x) {
    float y; asm("lg2.approx.f32 %0, %1;" : "=f"(y) : "f"(x)); return y;
}
__device__ __forceinline__ void pack_hl(float x, float y,
                                        uint32_t& hp, uint32_t& lp) {
    __half2 hh = __floats2half2_rn(x, y);
    __half2 ll = __floats2half2_rn(x - __half2float(__low2half(hh)),
                                   y - __half2float(__high2half(hh)));
    hp = *(uint32_t*)&hh; lp = *(uint32_t*)&ll;
}
__device__ __forceinline__ void split_store2(__half* hi, __half* lo,
                                             size_t idx, float x, float y) {
    uint32_t hp, lp;
    pack_hl(x, y, hp, lp);
    *(uint32_t*)(hi + idx) = hp;
    *(uint32_t*)(lo + idx) = lp;
}

// ---------------------------------------------------------------------------
// Split fp32 -> (hi, lo) fp16, elementwise
// ---------------------------------------------------------------------------
__global__ __launch_bounds__(256) void split_kernel(
    const float* __restrict__ src, __half* __restrict__ hi,
    __half* __restrict__ lo, int n2)
{
    for (int i = blockIdx.x * blockDim.x + threadIdx.x; i < n2;
         i += gridDim.x * blockDim.x) {
        float2 v = ((const float2*)src)[i];
        split_store2(hi, lo, (size_t)i * 2, v.x, v.y);
    }
}

// ---------------------------------------------------------------------------
// Transpose + fp16 cast: src [K][N] fp32 -> hiT [N][K] fp16 (hi only)
// ---------------------------------------------------------------------------
__global__ __launch_bounds__(256) void transpose_h_kernel(
    const float* __restrict__ src, __half* __restrict__ hiT, int K, int N)
{
    __shared__ float tile[32][33];
    const int tx = threadIdx.x, ty = threadIdx.y;   // (32, 8)
    const int n0 = blockIdx.x * 32, k0 = blockIdx.y * 32;

    #pragma unroll
    for (int i = 0; i < 4; ++i)
        tile[ty + i * 8][tx] = src[(size_t)(k0 + ty + i * 8) * N + n0 + tx];
    __syncthreads();

    #pragma unroll
    for (int i = 0; i < 4; ++i) {
        int n = n0 + ty + i * 8;
        hiT[(size_t)n * K + k0 + tx] = __float2half_rn(tile[tx][ty + i * 8]);
    }
}

// ---------------------------------------------------------------------------
// fp16 2-term split GEMM: C = A @ B + bias
// A = hi/lo fp16 [M][K]; B = hi fp16 transposed [Nc][K].
// CTA 128x128, BK=64 (fewer barriers), 256 threads, warp tile 32x64,
// cp.async 2-stage, 144B-padded rows (conflict-free ldsm).
// ---------------------------------------------------------------------------
#define AHI_OFF 0
#define ALO_OFF 18432
#define BHI_OFF 36864
#define STAGE_SZ 55296
static constexpr size_t GEMM_SMEM = 2 * STAGE_SZ;  // 110592

__global__ __launch_bounds__(256, 2) void gemm_mma_kernel(
    const __half* __restrict__ Ahi, const __half* __restrict__ Alo,
    const __half* __restrict__ BTh,
    const float* __restrict__ bias, float* __restrict__ C,
    __half* __restrict__ Chi, __half* __restrict__ Clo,
    int M, int Nc, int K)
{
    extern __shared__ char smc[];
    const uint32_t sbase = smem_to_u32(smc);
    const int tid = threadIdx.x;
    const int lane = tid & 31, wid = tid >> 5;
    const int wm = (wid & 3) * 32;
    const int wn = (wid >> 2) * 64;
    const int bm = blockIdx.y * 128, bn = blockIdx.x * 128;

    auto load_stage = [&](int k0, int buf) {
        uint32_t st = sbase + buf * STAGE_SZ;
        #pragma unroll
        for (int q = 0; q < 4; ++q) {
            int f = q * 256 + tid;
            int row = f >> 3, c = f & 7;
            uint32_t so = row * 144 + c * 16;
            size_t gA = (size_t)(bm + row) * K + k0 + c * 8;
            size_t gB = (size_t)(bn + row) * K + k0 + c * 8;
            cp16(st + AHI_OFF + so, Ahi + gA);
            cp16(st + ALO_OFF + so, Alo + gA);
            cp16(st + BHI_OFF + so, BTh + gB);
        }
    };

    float acc[2][8][4];
    #pragma unroll
    for (int a = 0; a < 2; ++a)
        #pragma unroll
        for (int b = 0; b < 8; ++b)
            #pragma unroll
            for (int c = 0; c < 4; ++c) acc[a][b][c] = 0.f;

    const int arow = wm + (lane & 15);
    const int brow = wn + (lane & 15);
    const int klb  = (lane >> 4) * 16;

    const int nit = K / 64;
    load_stage(0, 0);
    cp_commit();

    for (int i = 0; i < nit; ++i) {
        const int cur = i & 1;
        if (i + 1 < nit) { load_stage((i + 1) * 64, cur ^ 1); cp_commit(); }
        if (i + 1 < nit) cp_wait<1>(); else cp_wait<0>();
        __syncthreads();

        const uint32_t st = sbase + cur * STAGE_SZ;
        #pragma unroll
        for (int ks = 0; ks < 4; ++ks) {
            const uint32_t kb = ks * 32 + klb;
            uint32_t ah[2][4], al[2][4], bh[4][4];
            #pragma unroll
            for (int mt = 0; mt < 2; ++mt) {
                ldsm_x4(ah[mt], st + AHI_OFF + (arow + mt * 16) * 144 + kb);
                ldsm_x4(al[mt], st + ALO_OFF + (arow + mt * 16) * 144 + kb);
            }
            #pragma unroll
            for (int nt = 0; nt < 4; ++nt)
                ldsm_x4(bh[nt], st + BHI_OFF + (brow + nt * 16) * 144 + kb);

            #pragma unroll
            for (int mt = 0; mt < 2; ++mt)
                #pragma unroll
                for (int j = 0; j < 8; ++j)
                    mma_f16(acc[mt][j], ah[mt], bh[j >> 1][j & 1],
                            bh[j >> 1][(j & 1) + 2]);
            #pragma unroll
            for (int mt = 0; mt < 2; ++mt)
                #pragma unroll
                for (int j = 0; j < 8; ++j)
                    mma_f16(acc[mt][j], al[mt], bh[j >> 1][j & 1],
                            bh[j >> 1][(j & 1) + 2]);
        }
        __syncthreads();
    }

    // epilogue
    const int g = lane >> 2, tq = lane & 3;
    #pragma unroll
    for (int mt = 0; mt < 2; ++mt) {
        const int r0 = bm + wm + mt * 16 + g;
        #pragma unroll
        for (int j = 0; j < 8; ++j) {
            const int col = bn + wn + j * 8 + tq * 2;
            const float b0 = bias[col], b1 = bias[col + 1];
            float v00 = acc[mt][j][0] + b0, v01 = acc[mt][j][1] + b1;
            float v10 = acc[mt][j][2] + b0, v11 = acc[mt][j][3] + b1;
            if (C) {
                *(float2*)&C[(size_t)r0 * Nc + col] = make_float2(v00, v01);
                *(float2*)&C[(size_t)(r0 + 8) * Nc + col] = make_float2(v10, v11);
            } else {
                split_store2(Chi, Clo, (size_t)r0 * Nc + col, v00, v01);
                split_store2(Chi, Clo, (size_t)(r0 + 8) * Nc + col, v10, v11);
            }
        }
    }
}

// ---------------------------------------------------------------------------
// MMA attention: 128 queries per CTA, 64-key tiles, max-free two-pass softmax.
// Scores bounded (~|s|<=8) so exp(s) is fp32-safe without max subtraction.
// Q = hi/lo fp16; K,V = hi fp16 only.
// ---------------------------------------------------------------------------
#define ATT_QHI   0
#define ATT_QLO   18432
#define ATT_STG   36864
#define ATT_STAGE 18432
#define ATT_VOF   9216
#define ATT_CW    73728
#define ATT_SMEM  75776

__global__ __launch_bounds__(256, 2) void attn_mma_kernel(float* __restrict__ attn_mean)
{
    extern __shared__ char smc[];
    const uint32_t sb = smem_to_u32(smc);
    float* Cw = (float*)(smc + ATT_CW);
    const int tid = threadIdx.x, lane = tid & 31, wid = tid >> 5;
    const int g = lane >> 2, tg = lane & 3;
    const int h = blockIdx.y >> 1, b = blockIdx.y & 1;
    const int q0 = blockIdx.x * 128;
    const float CEXP = 0.18033688f;  // 0.125 * log2(e)
    const float MSCALE = 1.0f / (NHEADS * (float)NSEQ);

    auto loadQ = [&]() {
        #pragma unroll
        for (int i = 0; i < 4; ++i) {
            int c = i * 256 + tid; int r = c >> 3, ch = c & 7;
            size_t go = ((size_t)(b * NSEQ + q0 + r)) * TD + h * 192 + ch * 8;
            cp16(sb + ATT_QHI + r * 144 + ch * 16, g_qkvhi + go);
            cp16(sb + ATT_QLO + r * 144 + ch * 16, g_qkvlo + go);
        }
    };
    auto loadK = [&](int kt, int s) {
        uint32_t st = sb + ATT_STG + s * ATT_STAGE;
        #pragma unroll
        for (int i = 0; i < 2; ++i) {
            int c = i * 256 + tid; int r = c >> 3, ch = c & 7;
            size_t go = ((size_t)(b * NSEQ + kt * 64 + r)) * TD + h * 192 + 64 + ch * 8;
            cp16(st + r * 144 + ch * 16, g_qkvhi + go);
        }
    };
    auto loadKV = [&](int kt, int s) {
        loadK(kt, s);
        uint32_t st = sb + ATT_STG + s * ATT_STAGE + ATT_VOF;
        #pragma unroll
        for (int i = 0; i < 2; ++i) {
            int c = i * 256 + tid; int r = c >> 3, ch = c & 7;
            size_t go = ((size_t)(b * NSEQ + kt * 64 + r)) * TD + h * 192 + 128 + ch * 8;
            cp16(st + r * 144 + ch * 16, g_qkvhi + go);
        }
    };

    const uint32_t klb  = (lane >> 4) * 16;
    const uint32_t arow = wid * 16 + (lane & 15);
    const uint32_t brow = lane & 15;

    auto computeS = [&](uint32_t stg, float (*acc)[4]) {
        #pragma unroll
        for (int ks = 0; ks < 4; ++ks) {
            const uint32_t kb = ks * 32 + klb;
            uint32_t ah[4], al[4], bh[4][4];
            ldsm_x4(ah, sb + ATT_QHI + arow * 144 + kb);
            ldsm_x4(al, sb + ATT_QLO + arow * 144 + kb);
            #pragma unroll
            for (int nt = 0; nt < 4; ++nt)
                ldsm_x4(bh[nt], stg + (brow + nt * 16) * 144 + kb);
            #pragma unroll
            for (int nt = 0; nt < 4; ++nt)
                #pragma unroll
                for (int o = 0; o < 2; ++o)
                    mma_f16(acc[nt * 2 + o], ah, bh[nt][o], bh[nt][o + 2]);
            #pragma unroll
            for (int nt = 0; nt < 4; ++nt)
                #pragma unroll
                for (int o = 0; o < 2; ++o)
                    mma_f16(acc[nt * 2 + o], al, bh[nt][o], bh[nt][o + 2]);
        }
    };

    float l0 = 0.f, l1 = 0.f;

    // ================= PASS A: sumexp only (max-free) =================
    loadQ(); loadK(0, 0); cp_commit();
    loadK(1, 1); cp_commit();

    for (int kt = 0; kt < 32; ++kt) {
        cp_wait<1>();
        __syncthreads();
        const uint32_t stg = sb + ATT_STG + (kt & 1) * ATT_STAGE;

        float acc[8][4];
        #pragma unroll
        for (int j = 0; j < 8; ++j)
            #pragma unroll
            for (int x = 0; x < 4; ++x) acc[j][x] = 0.f;
        computeS(stg, acc);

        float s0 = 0.f, s1 = 0.f;
        #pragma unroll
        for (int j = 0; j < 8; ++j) {
            s0 += ex2(acc[j][0] * CEXP) + ex2(acc[j][1] * CEXP);
            s1 += ex2(acc[j][2] * CEXP) + ex2(acc[j][3] * CEXP);
        }
        l0 += s0; l1 += s1;

        __syncthreads();
        if (kt + 2 < 32) loadK(kt + 2, kt & 1);
        cp_commit();
    }

    // lane-group reduce (quad share rows)
    l0 += __shfl_xor_sync(0xffffffffu, l0, 1);
    l0 += __shfl_xor_sync(0xffffffffu, l0, 2);
    l1 += __shfl_xor_sync(0xffffffffu, l1, 1);
    l1 += __shfl_xor_sync(0xffffffffu, l1, 2);
    const float rlog0 = -lg2(l0), rlog1 = -lg2(l1);
    const float rl0 = 1.0f / l0, rl1 = 1.0f / l1;
    (void)rl0; (void)rl1;

    float ctx[8][4];
    #pragma unroll
    for (int j = 0; j < 8; ++j)
        #pragma unroll
        for (int x = 0; x < 4; ++x) ctx[j][x] = 0.f;

    // ================= PASS B =================
    loadKV(0, 0); cp_commit();
    loadKV(1, 1); cp_commit();

    for (int kt = 0; kt < 32; ++kt) {
        cp_wait<1>();
        __syncthreads();
        const uint32_t stg = sb + ATT_STG + (kt & 1) * ATT_STAGE;

        float acc[8][4];
        #pragma unroll
        for (int j = 0; j < 8; ++j)
            #pragma unroll
            for (int x = 0; x < 4; ++x) acc[j][x] = 0.f;
        computeS(stg, acc);

        // normalized probs in one fma+ex2; column sums
        #pragma unroll
        for (int j = 0; j < 8; ++j) {
            float p0 = ex2(fmaf(acc[j][0], CEXP, rlog0));
            float p1 = ex2(fmaf(acc[j][1], CEXP, rlog0));
            float p2 = ex2(fmaf(acc[j][2], CEXP, rlog1));
            float p3 = ex2(fmaf(acc[j][3], CEXP, rlog1));
            acc[j][0] = p0; acc[j][1] = p1; acc[j][2] = p2; acc[j][3] = p3;
            float c0 = p0 + p2, c1 = p1 + p3;
            c0 += __shfl_xor_sync(0xffffffffu, c0, 4);
            c0 += __shfl_xor_sync(0xffffffffu, c0, 8);
            c0 += __shfl_xor_sync(0xffffffffu, c0, 16);
            c1 += __shfl_xor_sync(0xffffffffu, c1, 4);
            c1 += __shfl_xor_sync(0xffffffffu, c1, 8);
            c1 += __shfl_xor_sync(0xffffffffu, c1, 16);
            if (lane < 4) {
                Cw[wid * 64 + j * 8 + lane * 2]     = c0;
                Cw[wid * 64 + j * 8 + lane * 2 + 1] = c1;
            }
        }

        // P @ V: P split hi/lo, V hi only
        #pragma unroll
        for (int kc = 0; kc < 4; ++kc) {
            const int j0 = kc * 2, j1 = j0 + 1;
            uint32_t aph[4], apl[4];
            pack_hl(acc[j0][0], acc[j0][1], aph[0], apl[0]);
            pack_hl(acc[j0][2], acc[j0][3], aph[1], apl[1]);
            pack_hl(acc[j1][0], acc[j1][1], aph[2], apl[2]);
            pack_hl(acc[j1][2], acc[j1][3], aph[3], apl[3]);
            #pragma unroll
            for (int dkt = 0; dkt < 4; ++dkt) {
                const uint32_t off = (kc * 16 + (lane & 15)) * 144 + dkt * 32
                                   + (lane >> 4) * 16;
                uint32_t vh[4];
                ldsm_x4_t(vh, stg + ATT_VOF + off);
                mma_f16(ctx[dkt * 2], aph, vh[0], vh[1]);
                mma_f16(ctx[dkt * 2], apl, vh[0], vh[1]);
                mma_f16(ctx[dkt * 2 + 1], aph, vh[2], vh[3]);
                mma_f16(ctx[dkt * 2 + 1], apl, vh[2], vh[3]);
            }
        }

        __syncthreads();
        if (tid < 64) {
            float tot = 0.f;
            #pragma unroll
            for (int w = 0; w < 8; ++w) tot += Cw[w * 64 + tid];
            atomicAdd(&attn_mean[b * NSEQ + kt * 64 + tid], tot * MSCALE);
        }
        if (kt + 2 < 32) loadKV(kt + 2, kt & 1);
        cp_commit();
    }

    // epilogue: write context hi/lo fp16 (B, N, H*dk layout)
    const int r0 = q0 + wid * 16 + g;
    #pragma unroll
    for (int nd = 0; nd < 8; ++nd) {
        const int col = h * 64 + nd * 8 + tg * 2;
        size_t i0 = ((size_t)(b * NSEQ + r0)) * DMODEL + col;
        split_store2(g_ctxhi, g_ctxlo, i0, ctx[nd][0], ctx[nd][1]);
        split_store2(g_ctxhi, g_ctxlo, i0 + 8 * DMODEL, ctx[nd][2], ctx[nd][3]);
    }
}

// ---------------------------------------------------------------------------
extern "C" void kernel_launch(void* const* d_in, const int* in_sizes, int n_in,
                              void* d_out, int out_size)
{
    const float* x     = (const float*)d_in[0];
    const float* w_qkv = (const float*)d_in[1];
    const float* b_qkv = (const float*)d_in[2];
    const float* w_out = (const float*)d_in[3];
    const float* b_out = (const float*)d_in[4];
    float* out = (float*)d_out;

    __half *qh, *ql, *xhi, *xlo, *ctxhi, *ctxlo, *wqh, *woh;
    cudaGetSymbolAddress((void**)&qh, g_qkvhi);
    cudaGetSymbolAddress((void**)&ql, g_qkvlo);
    cudaGetSymbolAddress((void**)&xhi, g_xhi);
    cudaGetSymbolAddress((void**)&xlo, g_xlo);
    cudaGetSymbolAddress((void**)&ctxhi, g_ctxhi);
    cudaGetSymbolAddress((void**)&ctxlo, g_ctxlo);
    cudaGetSymbolAddress((void**)&wqh, g_wqkvT_h);
    cudaGetSymbolAddress((void**)&woh, g_woutT_h);

    const int M = BDIM * NSEQ;                    // 4096
    float* attn_mean = out + (size_t)M * DMODEL;  // second output region

    cudaMemsetAsync(attn_mean, 0, (size_t)BDIM * NSEQ * sizeof(float));

    // prep: split input, cast+transpose weights (hi only)
    split_kernel<<<1024, 256>>>(x, xhi, xlo, M * DMODEL / 2);
    transpose_h_kernel<<<dim3(TD / 32, DMODEL / 32), dim3(32, 8)>>>(
        w_qkv, wqh, DMODEL, TD);
    transpose_h_kernel<<<dim3(DMODEL / 32, DMODEL / 32), dim3(32, 8)>>>(
        w_out, woh, DMODEL, DMODEL);

    cudaFuncSetAttribute(gemm_mma_kernel,
                         cudaFuncAttributeMaxDynamicSharedMemorySize,
                         (int)GEMM_SMEM);
    cudaFuncSetAttribute(attn_mma_kernel,
                         cudaFuncAttributeMaxDynamicSharedMemorySize,
                         ATT_SMEM);

    // QKV projection -> split fp16 output
    gemm_mma_kernel<<<dim3(TD / 128, M / 128), 256, GEMM_SMEM>>>(
        xhi, xlo, wqh, b_qkv, nullptr, qh, ql, M, TD, DMODEL);

    // attention (mma, max-free two-pass)
    attn_mma_kernel<<<dim3(NSEQ / 128, NHEADS * BDIM), 256, ATT_SMEM>>>(attn_mean);

    // output projection -> fp32 final output
    gemm_mma_kernel<<<dim3(DMODEL / 128, M / 128), 256, GEMM_SMEM>>>(
        ctxhi, ctxlo, woh, b_out, out, nullptr, nullptr, M, DMODEL, DMODEL);
}

// round 7
// speedup vs baseline: 4.4075x; 1.0256x over previous
#include <cuda_runtime.h>
#include <cuda_fp16.h>
#include <cstdint>

#define BDIM   2
#define NSEQ   2048
#define DMODEL 1024
#define NHEADS 16
#define DKH    64
#define TD     3072   // 3*DMODEL

// ---------------------------------------------------------------------------
// Scratch (static device globals: allocation-free rule)
// ---------------------------------------------------------------------------
__device__ __half g_qkvhi[(size_t)BDIM * NSEQ * TD];
__device__ __half g_qkvlo[(size_t)BDIM * NSEQ * TD];
__device__ __half g_xhi[(size_t)BDIM * NSEQ * DMODEL];
__device__ __half g_xlo[(size_t)BDIM * NSEQ * DMODEL];
__device__ __half g_ctxhi[(size_t)BDIM * NSEQ * DMODEL];
__device__ __half g_ctxlo[(size_t)BDIM * NSEQ * DMODEL];
__device__ __half g_wqkvT_h[(size_t)TD * DMODEL];   // [N=3072][K=1024] hi only
__device__ __half g_woutT_h[(size_t)DMODEL * DMODEL];

// ---------------------------------------------------------------------------
// PTX helpers (baseline ISA only: compiles under compute_103)
// ---------------------------------------------------------------------------
__device__ __forceinline__ uint32_t smem_to_u32(const void* p) {
    uint32_t a;
    asm("{ .reg .u64 t; cvta.to.shared.u64 t, %1; cvt.u32.u64 %0, t; }"
        : "=r"(a) : "l"(p));
    return a;
}
__device__ __forceinline__ void cp16(uint32_t s, const void* g) {
    asm volatile("cp.async.ca.shared.global [%0], [%1], 16;" :: "r"(s), "l"(g));
}
__device__ __forceinline__ void cp_commit() {
    asm volatile("cp.async.commit_group;");
}
template <int N> __device__ __forceinline__ void cp_wait() {
    asm volatile("cp.async.wait_group %0;" :: "n"(N));
}
__device__ __forceinline__ void ldsm_x4(uint32_t* r, uint32_t addr) {
    asm volatile("ldmatrix.sync.aligned.m8n8.x4.shared.b16 {%0,%1,%2,%3}, [%4];"
        : "=r"(r[0]), "=r"(r[1]), "=r"(r[2]), "=r"(r[3]) : "r"(addr));
}
__device__ __forceinline__ void ldsm_x4_t(uint32_t* r, uint32_t addr) {
    asm volatile("ldmatrix.sync.aligned.m8n8.x4.trans.shared.b16 {%0,%1,%2,%3}, [%4];"
        : "=r"(r[0]), "=r"(r[1]), "=r"(r[2]), "=r"(r[3]) : "r"(addr));
}
__device__ __forceinline__ void mma_f16(float* d, const uint32_t* a,
                                        uint32_t b0, uint32_t b1) {
    asm volatile(
        "mma.sync.aligned.m16n8k16.row.col.f32.f16.f16.f32 "
        "{%0,%1,%2,%3}, {%4,%5,%6,%7}, {%8,%9}, {%0,%1,%2,%3};"
        : "+f"(d[0]), "+f"(d[1]), "+f"(d[2]), "+f"(d[3])
        : "r"(a[0]), "r"(a[1]), "r"(a[2]), "r"(a[3]), "r"(b0), "r"(b1));
}
__device__ __forceinline__ float ex2(float x) {
    float y; asm("ex2.approx.f32 %0, %1;" : "=f"(y) : "f"(x)); return y;
}
__device__ __forceinline__ float lg2(float x) {
    float y; asm("lg2.approx.f32 %0, %1;" : "=f"(y) : "f"(x)); return y;
}
__device__ __forceinline__ void pack_hl(float x, float y,
                                        uint32_t& hp, uint32_t& lp) {
    __half2 hh = __floats2half2_rn(x, y);
    __half2 ll = __floats2half2_rn(x - __half2float(__low2half(hh)),
                                   y - __half2float(__high2half(hh)));
    hp = *(uint32_t*)&hh; lp = *(uint32_t*)&ll;
}
__device__ __forceinline__ void split_store2(__half* hi, __half* lo,
                                             size_t idx, float x, float y) {
    uint32_t hp, lp;
    pack_hl(x, y, hp, lp);
    *(uint32_t*)(hi + idx) = hp;
    *(uint32_t*)(lo + idx) = lp;
}

// ---------------------------------------------------------------------------
// Split fp32 -> (hi, lo) fp16, elementwise
// ---------------------------------------------------------------------------
__global__ __launch_bounds__(256) void split_kernel(
    const float* __restrict__ src, __half* __restrict__ hi,
    __half* __restrict__ lo, int n2)
{
    for (int i = blockIdx.x * blockDim.x + threadIdx.x; i < n2;
         i += gridDim.x * blockDim.x) {
        float2 v = ((const float2*)src)[i];
        split_store2(hi, lo, (size_t)i * 2, v.x, v.y);
    }
}

// ---------------------------------------------------------------------------
// Transpose + fp16 cast: src [K][N] fp32 -> hiT [N][K] fp16 (hi only)
// ---------------------------------------------------------------------------
__global__ __launch_bounds__(256) void transpose_h_kernel(
    const float* __restrict__ src, __half* __restrict__ hiT, int K, int N)
{
    __shared__ float tile[32][33];
    const int tx = threadIdx.x, ty = threadIdx.y;   // (32, 8)
    const int n0 = blockIdx.x * 32, k0 = blockIdx.y * 32;

    #pragma unroll
    for (int i = 0; i < 4; ++i)
        tile[ty + i * 8][tx] = src[(size_t)(k0 + ty + i * 8) * N + n0 + tx];
    __syncthreads();

    #pragma unroll
    for (int i = 0; i < 4; ++i) {
        int n = n0 + ty + i * 8;
        hiT[(size_t)n * K + k0 + tx] = __float2half_rn(tile[tx][ty + i * 8]);
    }
}

// ---------------------------------------------------------------------------
// fp16 2-term split GEMM (R5-proven config): C = A @ B + bias
// A = hi/lo fp16 [M][K]; B = hi fp16 transposed [Nc][K].
// CTA 128x128, BK=32, 256 threads, warp tile 32x64, cp.async 2-stage,
// hoisted per-thread global pointers, 80B-padded rows.
// ---------------------------------------------------------------------------
#define AHI_OFF 0
#define ALO_OFF 10240
#define BHI_OFF 20480
#define STAGE_SZ 30720
static constexpr size_t GEMM_SMEM = 2 * STAGE_SZ;  // 61440

__global__ __launch_bounds__(256, 2) void gemm_mma_kernel(
    const __half* __restrict__ Ahi, const __half* __restrict__ Alo,
    const __half* __restrict__ BTh,
    const float* __restrict__ bias, float* __restrict__ C,
    __half* __restrict__ Chi, __half* __restrict__ Clo,
    int M, int Nc, int K)
{
    extern __shared__ char smc[];
    const uint32_t sbase = smem_to_u32(smc);
    const int tid = threadIdx.x;
    const int lane = tid & 31, wid = tid >> 5;
    const int wm = (wid & 3) * 32;
    const int wn = (wid >> 2) * 64;
    const int bm = blockIdx.y * 128, bn = blockIdx.x * 128;

    const int lrow = tid >> 1;
    const int lc   = (tid & 1) * 2;

    const __half* gAh = Ahi + (size_t)(bm + lrow) * K + lc * 8;
    const __half* gAl = Alo + (size_t)(bm + lrow) * K + lc * 8;
    const __half* gBh = BTh + (size_t)(bn + lrow) * K + lc * 8;

    const uint32_t sRow = lrow * 80 + lc * 16;

    auto load_stage = [&](int k0, int buf) {
        uint32_t st = sbase + buf * STAGE_SZ;
        cp16(st + AHI_OFF + sRow,      gAh + k0);
        cp16(st + AHI_OFF + sRow + 16, gAh + k0 + 8);
        cp16(st + ALO_OFF + sRow,      gAl + k0);
        cp16(st + ALO_OFF + sRow + 16, gAl + k0 + 8);
        cp16(st + BHI_OFF + sRow,      gBh + k0);
        cp16(st + BHI_OFF + sRow + 16, gBh + k0 + 8);
    };

    float acc[2][8][4];
    #pragma unroll
    for (int a = 0; a < 2; ++a)
        #pragma unroll
        for (int b = 0; b < 8; ++b)
            #pragma unroll
            for (int c = 0; c < 4; ++c) acc[a][b][c] = 0.f;

    const int arow = wm + (lane & 15);
    const int brow = wn + (lane & 15);
    const int klb  = (lane >> 4) * 16;

    const int nit = K / 32;
    load_stage(0, 0);
    cp_commit();

    for (int i = 0; i < nit; ++i) {
        const int cur = i & 1;
        if (i + 1 < nit) { load_stage((i + 1) * 32, cur ^ 1); cp_commit(); }
        if (i + 1 < nit) cp_wait<1>(); else cp_wait<0>();
        __syncthreads();

        const uint32_t st = sbase + cur * STAGE_SZ;
        #pragma unroll
        for (int ks = 0; ks < 2; ++ks) {
            const uint32_t kb = ks * 32 + klb;
            uint32_t ah[2][4], al[2][4], bh[4][4];
            #pragma unroll
            for (int mt = 0; mt < 2; ++mt) {
                ldsm_x4(ah[mt], st + AHI_OFF + (arow + mt * 16) * 80 + kb);
                ldsm_x4(al[mt], st + ALO_OFF + (arow + mt * 16) * 80 + kb);
            }
            #pragma unroll
            for (int nt = 0; nt < 4; ++nt)
                ldsm_x4(bh[nt], st + BHI_OFF + (brow + nt * 16) * 80 + kb);

            #pragma unroll
            for (int mt = 0; mt < 2; ++mt)
                #pragma unroll
                for (int j = 0; j < 8; ++j)
                    mma_f16(acc[mt][j], ah[mt], bh[j >> 1][j & 1],
                            bh[j >> 1][(j & 1) + 2]);
            #pragma unroll
            for (int mt = 0; mt < 2; ++mt)
                #pragma unroll
                for (int j = 0; j < 8; ++j)
                    mma_f16(acc[mt][j], al[mt], bh[j >> 1][j & 1],
                            bh[j >> 1][(j & 1) + 2]);
        }
        __syncthreads();
    }

    // epilogue
    const int g = lane >> 2, tq = lane & 3;
    #pragma unroll
    for (int mt = 0; mt < 2; ++mt) {
        const int r0 = bm + wm + mt * 16 + g;
        #pragma unroll
        for (int j = 0; j < 8; ++j) {
            const int col = bn + wn + j * 8 + tq * 2;
            const float b0 = bias[col], b1 = bias[col + 1];
            float v00 = acc[mt][j][0] + b0, v01 = acc[mt][j][1] + b1;
            float v10 = acc[mt][j][2] + b0, v11 = acc[mt][j][3] + b1;
            if (C) {
                *(float2*)&C[(size_t)r0 * Nc + col] = make_float2(v00, v01);
                *(float2*)&C[(size_t)(r0 + 8) * Nc + col] = make_float2(v10, v11);
            } else {
                split_store2(Chi, Clo, (size_t)r0 * Nc + col, v00, v01);
                split_store2(Chi, Clo, (size_t)(r0 + 8) * Nc + col, v10, v11);
            }
        }
    }
}

// ---------------------------------------------------------------------------
// MMA attention: 128 queries per CTA, 64-key tiles, max-free two-pass softmax.
// Pass A uses Q-hi only (normalizer tolerates ~1e-4); pass B full 2-term.
// Column sums: 3-shfl quad reduce then direct atomics (no smem staging).
// ---------------------------------------------------------------------------
#define ATT_QHI   0
#define ATT_QLO   18432
#define ATT_STG   36864
#define ATT_STAGE 18432
#define ATT_VOF   9216
#define ATT_SMEM  73728

__global__ __launch_bounds__(256, 2) void attn_mma_kernel(float* __restrict__ attn_mean)
{
    extern __shared__ char smc[];
    const uint32_t sb = smem_to_u32(smc);
    const int tid = threadIdx.x, lane = tid & 31, wid = tid >> 5;
    const int g = lane >> 2, tg = lane & 3;
    const int h = blockIdx.y >> 1, b = blockIdx.y & 1;
    const int q0 = blockIdx.x * 128;
    const float CEXP = 0.18033688f;  // 0.125 * log2(e)
    const float MSCALE = 1.0f / (NHEADS * (float)NSEQ);

    // hoisted per-thread loader bases (r, ch fixed per thread slot)
    const int lr = tid >> 3, lch = tid & 7;          // r = lr + i*32, ch = lch
    const size_t rowQ  = ((size_t)(b * NSEQ + q0 + lr)) * TD + h * 192 + lch * 8;
    const size_t rowKV = ((size_t)(b * NSEQ + lr)) * TD + h * 192 + lch * 8;
    const uint32_t soff = lr * 144 + lch * 16;
    const size_t KTSTEP = (size_t)64 * TD;

    auto loadQ = [&]() {
        #pragma unroll
        for (int i = 0; i < 4; ++i) {
            size_t go = rowQ + (size_t)i * 32 * TD;
            cp16(sb + ATT_QHI + soff + i * 32 * 144, g_qkvhi + go);
            cp16(sb + ATT_QLO + soff + i * 32 * 144, g_qkvlo + go);
        }
    };
    auto loadK = [&](int kt, int s) {
        uint32_t st = sb + ATT_STG + s * ATT_STAGE;
        size_t base = rowKV + (size_t)kt * KTSTEP + 64;
        cp16(st + soff,            g_qkvhi + base);
        cp16(st + soff + 32 * 144, g_qkvhi + base + 32 * TD);
    };
    auto loadKV = [&](int kt, int s) {
        uint32_t st = sb + ATT_STG + s * ATT_STAGE;
        size_t base = rowKV + (size_t)kt * KTSTEP + 64;
        cp16(st + soff,            g_qkvhi + base);
        cp16(st + soff + 32 * 144, g_qkvhi + base + 32 * TD);
        cp16(st + ATT_VOF + soff,            g_qkvhi + base + 64);
        cp16(st + ATT_VOF + soff + 32 * 144, g_qkvhi + base + 64 + 32 * TD);
    };

    const uint32_t klb  = (lane >> 4) * 16;
    const uint32_t arow = wid * 16 + (lane & 15);
    const uint32_t brow = lane & 15;

    auto computeS = [&](uint32_t stg, float (*acc)[4], bool full) {
        #pragma unroll
        for (int ks = 0; ks < 4; ++ks) {
            const uint32_t kb = ks * 32 + klb;
            uint32_t ah[4], bh[4][4];
            ldsm_x4(ah, sb + ATT_QHI + arow * 144 + kb);
            #pragma unroll
            for (int nt = 0; nt < 4; ++nt)
                ldsm_x4(bh[nt], stg + (brow + nt * 16) * 144 + kb);
            #pragma unroll
            for (int nt = 0; nt < 4; ++nt)
                #pragma unroll
                for (int o = 0; o < 2; ++o)
                    mma_f16(acc[nt * 2 + o], ah, bh[nt][o], bh[nt][o + 2]);
            if (full) {
                uint32_t al[4];
                ldsm_x4(al, sb + ATT_QLO + arow * 144 + kb);
                #pragma unroll
                for (int nt = 0; nt < 4; ++nt)
                    #pragma unroll
                    for (int o = 0; o < 2; ++o)
                        mma_f16(acc[nt * 2 + o], al, bh[nt][o], bh[nt][o + 2]);
            }
        }
    };

    float l0 = 0.f, l1 = 0.f;

    // ================= PASS A: sumexp only (max-free, Q-hi only) ==========
    loadQ(); loadK(0, 0); cp_commit();
    loadK(1, 1); cp_commit();

    for (int kt = 0; kt < 32; ++kt) {
        cp_wait<1>();
        __syncthreads();
        const uint32_t stg = sb + ATT_STG + (kt & 1) * ATT_STAGE;

        float acc[8][4];
        #pragma unroll
        for (int j = 0; j < 8; ++j)
            #pragma unroll
            for (int x = 0; x < 4; ++x) acc[j][x] = 0.f;
        computeS(stg, acc, false);

        #pragma unroll
        for (int j = 0; j < 8; ++j) {
            l0 += ex2(acc[j][0] * CEXP) + ex2(acc[j][1] * CEXP);
            l1 += ex2(acc[j][2] * CEXP) + ex2(acc[j][3] * CEXP);
        }

        __syncthreads();
        if (kt + 2 < 32) loadK(kt + 2, kt & 1);
        cp_commit();
    }

    // quad reduce (4 lanes share each row)
    l0 += __shfl_xor_sync(0xffffffffu, l0, 1);
    l0 += __shfl_xor_sync(0xffffffffu, l0, 2);
    l1 += __shfl_xor_sync(0xffffffffu, l1, 1);
    l1 += __shfl_xor_sync(0xffffffffu, l1, 2);
    const float rlog0 = -lg2(l0), rlog1 = -lg2(l1);

    float ctx[8][4];
    #pragma unroll
    for (int j = 0; j < 8; ++j)
        #pragma unroll
        for (int x = 0; x < 4; ++x) ctx[j][x] = 0.f;

    // ================= PASS B =================
    loadKV(0, 0); cp_commit();
    loadKV(1, 1); cp_commit();

    for (int kt = 0; kt < 32; ++kt) {
        cp_wait<1>();
        __syncthreads();
        const uint32_t stg = sb + ATT_STG + (kt & 1) * ATT_STAGE;

        float acc[8][4];
        #pragma unroll
        for (int j = 0; j < 8; ++j)
            #pragma unroll
            for (int x = 0; x < 4; ++x) acc[j][x] = 0.f;
        computeS(stg, acc, true);

        // normalized probs; column sums -> direct atomics from lanes 0-3
        float* amrow = &attn_mean[b * NSEQ + kt * 64];
        #pragma unroll
        for (int j = 0; j < 8; ++j) {
            float p0 = ex2(fmaf(acc[j][0], CEXP, rlog0));
            float p1 = ex2(fmaf(acc[j][1], CEXP, rlog0));
            float p2 = ex2(fmaf(acc[j][2], CEXP, rlog1));
            float p3 = ex2(fmaf(acc[j][3], CEXP, rlog1));
            acc[j][0] = p0; acc[j][1] = p1; acc[j][2] = p2; acc[j][3] = p3;
            float c0 = p0 + p2, c1 = p1 + p3;
            c0 += __shfl_xor_sync(0xffffffffu, c0, 4);
            c0 += __shfl_xor_sync(0xffffffffu, c0, 8);
            c0 += __shfl_xor_sync(0xffffffffu, c0, 16);
            c1 += __shfl_xor_sync(0xffffffffu, c1, 4);
            c1 += __shfl_xor_sync(0xffffffffu, c1, 8);
            c1 += __shfl_xor_sync(0xffffffffu, c1, 16);
            if (lane < 4) {
                atomicAdd(&amrow[j * 8 + lane * 2],     c0 * MSCALE);
                atomicAdd(&amrow[j * 8 + lane * 2 + 1], c1 * MSCALE);
            }
        }

        // P @ V: P split hi/lo, V hi only
        #pragma unroll
        for (int kc = 0; kc < 4; ++kc) {
            const int j0 = kc * 2, j1 = j0 + 1;
            uint32_t aph[4], apl[4];
            pack_hl(acc[j0][0], acc[j0][1], aph[0], apl[0]);
            pack_hl(acc[j0][2], acc[j0][3], aph[1], apl[1]);
            pack_hl(acc[j1][0], acc[j1][1], aph[2], apl[2]);
            pack_hl(acc[j1][2], acc[j1][3], aph[3], apl[3]);
            #pragma unroll
            for (int dkt = 0; dkt < 4; ++dkt) {
                const uint32_t off = (kc * 16 + (lane & 15)) * 144 + dkt * 32
                                   + (lane >> 4) * 16;
                uint32_t vh[4];
                ldsm_x4_t(vh, stg + ATT_VOF + off);
                mma_f16(ctx[dkt * 2], aph, vh[0], vh[1]);
                mma_f16(ctx[dkt * 2], apl, vh[0], vh[1]);
                mma_f16(ctx[dkt * 2 + 1], aph, vh[2], vh[3]);
                mma_f16(ctx[dkt * 2 + 1], apl, vh[2], vh[3]);
            }
        }

        __syncthreads();
        if (kt + 2 < 32) loadKV(kt + 2, kt & 1);
        cp_commit();
    }

    // epilogue: write context hi/lo fp16 (B, N, H*dk layout)
    const int r0 = q0 + wid * 16 + g;
    #pragma unroll
    for (int nd = 0; nd < 8; ++nd) {
        const int col = h * 64 + nd * 8 + tg * 2;
        size_t i0 = ((size_t)(b * NSEQ + r0)) * DMODEL + col;
        split_store2(g_ctxhi, g_ctxlo, i0, ctx[nd][0], ctx[nd][1]);
        split_store2(g_ctxhi, g_ctxlo, i0 + 8 * DMODEL, ctx[nd][2], ctx[nd][3]);
    }
}

// ---------------------------------------------------------------------------
extern "C" void kernel_launch(void* const* d_in, const int* in_sizes, int n_in,
                              void* d_out, int out_size)
{
    const float* x     = (const float*)d_in[0];
    const float* w_qkv = (const float*)d_in[1];
    const float* b_qkv = (const float*)d_in[2];
    const float* w_out = (const float*)d_in[3];
    const float* b_out = (const float*)d_in[4];
    float* out = (float*)d_out;

    __half *qh, *ql, *xhi, *xlo, *ctxhi, *ctxlo, *wqh, *woh;
    cudaGetSymbolAddress((void**)&qh, g_qkvhi);
    cudaGetSymbolAddress((void**)&ql, g_qkvlo);
    cudaGetSymbolAddress((void**)&xhi, g_xhi);
    cudaGetSymbolAddress((void**)&xlo, g_xlo);
    cudaGetSymbolAddress((void**)&ctxhi, g_ctxhi);
    cudaGetSymbolAddress((void**)&ctxlo, g_ctxlo);
    cudaGetSymbolAddress((void**)&wqh, g_wqkvT_h);
    cudaGetSymbolAddress((void**)&woh, g_woutT_h);

    const int M = BDIM * NSEQ;                    // 4096
    float* attn_mean = out + (size_t)M * DMODEL;  // second output region

    cudaMemsetAsync(attn_mean, 0, (size_t)BDIM * NSEQ * sizeof(float));

    // prep: split input, cast+transpose weights (hi only)
    split_kernel<<<1024, 256>>>(x, xhi, xlo, M * DMODEL / 2);
    transpose_h_kernel<<<dim3(TD / 32, DMODEL / 32), dim3(32, 8)>>>(
        w_qkv, wqh, DMODEL, TD);
    transpose_h_kernel<<<dim3(DMODEL / 32, DMODEL / 32), dim3(32, 8)>>>(
        w_out, woh, DMODEL, DMODEL);

    cudaFuncSetAttribute(gemm_mma_kernel,
                         cudaFuncAttributeMaxDynamicSharedMemorySize,
                         (int)GEMM_SMEM);
    cudaFuncSetAttribute(attn_mma_kernel,
                         cudaFuncAttributeMaxDynamicSharedMemorySize,
                         ATT_SMEM);

    // QKV projection -> split fp16 output
    gemm_mma_kernel<<<dim3(TD / 128, M / 128), 256, GEMM_SMEM>>>(
        xhi, xlo, wqh, b_qkv, nullptr, qh, ql, M, TD, DMODEL);

    // attention (mma, max-free two-pass)
    attn_mma_kernel<<<dim3(NSEQ / 128, NHEADS * BDIM), 256, ATT_SMEM>>>(attn_mean);

    // output projection -> fp32 final output
    gemm_mma_kernel<<<dim3(DMODEL / 128, M / 128), 256, GEMM_SMEM>>>(
        ctxhi, ctxlo, woh, b_out, out, nullptr, nullptr, M, DMODEL, DMODEL);
}

// round 8
// speedup vs baseline: 4.7828x; 1.0852x over previous
#include <cuda_runtime.h>
#include <cuda_fp16.h>
#include <cstdint>

#define BDIM   2
#define NSEQ   2048
#define DMODEL 1024
#define NHEADS 16
#define DKH    64
#define TD     3072   // 3*DMODEL

// ---------------------------------------------------------------------------
// Scratch (static device globals: allocation-free rule)
// ---------------------------------------------------------------------------
__device__ __half g_qkvhi[(size_t)BDIM * NSEQ * TD];
__device__ __half g_qkvlo[(size_t)BDIM * NSEQ * TD];
__device__ __half g_xhi[(size_t)BDIM * NSEQ * DMODEL];
__device__ __half g_xlo[(size_t)BDIM * NSEQ * DMODEL];
__device__ __half g_ctxhi[(size_t)BDIM * NSEQ * DMODEL];
__device__ __half g_ctxlo[(size_t)BDIM * NSEQ * DMODEL];
__device__ __half g_wqkvT_h[(size_t)TD * DMODEL];   // [N=3072][K=1024] hi only
__device__ __half g_woutT_h[(size_t)DMODEL * DMODEL];

// ---------------------------------------------------------------------------
// PTX helpers (baseline ISA only: compiles under compute_103)
// ---------------------------------------------------------------------------
__device__ __forceinline__ uint32_t smem_to_u32(const void* p) {
    uint32_t a;
    asm("{ .reg .u64 t; cvta.to.shared.u64 t, %1; cvt.u32.u64 %0, t; }"
        : "=r"(a) : "l"(p));
    return a;
}
__device__ __forceinline__ void cp16(uint32_t s, const void* g) {
    asm volatile("cp.async.ca.shared.global [%0], [%1], 16;" :: "r"(s), "l"(g));
}
__device__ __forceinline__ void cp_commit() {
    asm volatile("cp.async.commit_group;");
}
template <int N> __device__ __forceinline__ void cp_wait() {
    asm volatile("cp.async.wait_group %0;" :: "n"(N));
}
__device__ __forceinline__ void ldsm_x4(uint32_t* r, uint32_t addr) {
    asm volatile("ldmatrix.sync.aligned.m8n8.x4.shared.b16 {%0,%1,%2,%3}, [%4];"
        : "=r"(r[0]), "=r"(r[1]), "=r"(r[2]), "=r"(r[3]) : "r"(addr));
}
__device__ __forceinline__ void ldsm_x4_t(uint32_t* r, uint32_t addr) {
    asm volatile("ldmatrix.sync.aligned.m8n8.x4.trans.shared.b16 {%0,%1,%2,%3}, [%4];"
        : "=r"(r[0]), "=r"(r[1]), "=r"(r[2]), "=r"(r[3]) : "r"(addr));
}
__device__ __forceinline__ void mma_f16(float* d, const uint32_t* a,
                                        uint32_t b0, uint32_t b1) {
    asm volatile(
        "mma.sync.aligned.m16n8k16.row.col.f32.f16.f16.f32 "
        "{%0,%1,%2,%3}, {%4,%5,%6,%7}, {%8,%9}, {%0,%1,%2,%3};"
        : "+f"(d[0]), "+f"(d[1]), "+f"(d[2]), "+f"(d[3])
        : "r"(a[0]), "r"(a[1]), "r"(a[2]), "r"(a[3]), "r"(b0), "r"(b1));
}
__device__ __forceinline__ float ex2(float x) {
    float y; asm("ex2.approx.f32 %0, %1;" : "=f"(y) : "f"(x)); return y;
}
__device__ __forceinline__ float lg2(float x) {
    float y; asm("lg2.approx.f32 %0, %1;" : "=f"(y) : "f"(x)); return y;
}
// pack (lo, hi) floats into one f16x2 register
__device__ __forceinline__ uint32_t pack_h2(float lo, float hi) {
    uint32_t p;
    asm("cvt.rn.f16x2.f32 %0, %1, %2;" : "=r"(p) : "f"(hi), "f"(lo));
    return p;
}
// vectorized exp2: returns f16x2{exp2(lo), exp2(hi)}
__device__ __forceinline__ uint32_t ex2_h2(float lo, float hi) {
    uint32_t p, r;
    asm("cvt.rn.f16x2.f32 %0, %1, %2;" : "=r"(p) : "f"(hi), "f"(lo));
    asm("ex2.approx.f16x2 %0, %1;" : "=r"(r) : "r"(p));
    return r;
}
__device__ __forceinline__ void pack_hl(float x, float y,
                                        uint32_t& hp, uint32_t& lp) {
    __half2 hh = __floats2half2_rn(x, y);
    __half2 ll = __floats2half2_rn(x - __half2float(__low2half(hh)),
                                   y - __half2float(__high2half(hh)));
    hp = *(uint32_t*)&hh; lp = *(uint32_t*)&ll;
}
__device__ __forceinline__ void split_store2(__half* hi, __half* lo,
                                             size_t idx, float x, float y) {
    uint32_t hp, lp;
    pack_hl(x, y, hp, lp);
    *(uint32_t*)(hi + idx) = hp;
    *(uint32_t*)(lo + idx) = lp;
}

// ---------------------------------------------------------------------------
// Split fp32 -> (hi, lo) fp16, elementwise
// ---------------------------------------------------------------------------
__global__ __launch_bounds__(256) void split_kernel(
    const float* __restrict__ src, __half* __restrict__ hi,
    __half* __restrict__ lo, int n2)
{
    for (int i = blockIdx.x * blockDim.x + threadIdx.x; i < n2;
         i += gridDim.x * blockDim.x) {
        float2 v = ((const float2*)src)[i];
        split_store2(hi, lo, (size_t)i * 2, v.x, v.y);
    }
}

// ---------------------------------------------------------------------------
// Transpose + fp16 cast: src [K][N] fp32 -> hiT [N][K] fp16 (hi only)
// ---------------------------------------------------------------------------
__global__ __launch_bounds__(256) void transpose_h_kernel(
    const float* __restrict__ src, __half* __restrict__ hiT, int K, int N)
{
    __shared__ float tile[32][33];
    const int tx = threadIdx.x, ty = threadIdx.y;   // (32, 8)
    const int n0 = blockIdx.x * 32, k0 = blockIdx.y * 32;

    #pragma unroll
    for (int i = 0; i < 4; ++i)
        tile[ty + i * 8][tx] = src[(size_t)(k0 + ty + i * 8) * N + n0 + tx];
    __syncthreads();

    #pragma unroll
    for (int i = 0; i < 4; ++i) {
        int n = n0 + ty + i * 8;
        hiT[(size_t)n * K + k0 + tx] = __float2half_rn(tile[tx][ty + i * 8]);
    }
}

// ---------------------------------------------------------------------------
// fp16 2-term split GEMM (R5-proven config): C = A @ B + bias
// A = hi/lo fp16 [M][K]; B = hi fp16 transposed [Nc][K].
// CTA 128x128, BK=32, 256 threads, warp tile 32x64, cp.async 2-stage,
// hoisted per-thread global pointers, 80B-padded rows.
// ---------------------------------------------------------------------------
#define AHI_OFF 0
#define ALO_OFF 10240
#define BHI_OFF 20480
#define STAGE_SZ 30720
static constexpr size_t GEMM_SMEM = 2 * STAGE_SZ;  // 61440

__global__ __launch_bounds__(256, 2) void gemm_mma_kernel(
    const __half* __restrict__ Ahi, const __half* __restrict__ Alo,
    const __half* __restrict__ BTh,
    const float* __restrict__ bias, float* __restrict__ C,
    __half* __restrict__ Chi, __half* __restrict__ Clo,
    int M, int Nc, int K)
{
    extern __shared__ char smc[];
    const uint32_t sbase = smem_to_u32(smc);
    const int tid = threadIdx.x;
    const int lane = tid & 31, wid = tid >> 5;
    const int wm = (wid & 3) * 32;
    const int wn = (wid >> 2) * 64;
    const int bm = blockIdx.y * 128, bn = blockIdx.x * 128;

    const int lrow = tid >> 1;
    const int lc   = (tid & 1) * 2;

    const __half* gAh = Ahi + (size_t)(bm + lrow) * K + lc * 8;
    const __half* gAl = Alo + (size_t)(bm + lrow) * K + lc * 8;
    const __half* gBh = BTh + (size_t)(bn + lrow) * K + lc * 8;

    const uint32_t sRow = lrow * 80 + lc * 16;

    auto load_stage = [&](int k0, int buf) {
        uint32_t st = sbase + buf * STAGE_SZ;
        cp16(st + AHI_OFF + sRow,      gAh + k0);
        cp16(st + AHI_OFF + sRow + 16, gAh + k0 + 8);
        cp16(st + ALO_OFF + sRow,      gAl + k0);
        cp16(st + ALO_OFF + sRow + 16, gAl + k0 + 8);
        cp16(st + BHI_OFF + sRow,      gBh + k0);
        cp16(st + BHI_OFF + sRow + 16, gBh + k0 + 8);
    };

    float acc[2][8][4];
    #pragma unroll
    for (int a = 0; a < 2; ++a)
        #pragma unroll
        for (int b = 0; b < 8; ++b)
            #pragma unroll
            for (int c = 0; c < 4; ++c) acc[a][b][c] = 0.f;

    const int arow = wm + (lane & 15);
    const int brow = wn + (lane & 15);
    const int klb  = (lane >> 4) * 16;

    const int nit = K / 32;
    load_stage(0, 0);
    cp_commit();

    for (int i = 0; i < nit; ++i) {
        const int cur = i & 1;
        if (i + 1 < nit) { load_stage((i + 1) * 32, cur ^ 1); cp_commit(); }
        if (i + 1 < nit) cp_wait<1>(); else cp_wait<0>();
        __syncthreads();

        const uint32_t st = sbase + cur * STAGE_SZ;
        #pragma unroll
        for (int ks = 0; ks < 2; ++ks) {
            const uint32_t kb = ks * 32 + klb;
            uint32_t ah[2][4], al[2][4], bh[4][4];
            #pragma unroll
            for (int mt = 0; mt < 2; ++mt) {
                ldsm_x4(ah[mt], st + AHI_OFF + (arow + mt * 16) * 80 + kb);
                ldsm_x4(al[mt], st + ALO_OFF + (arow + mt * 16) * 80 + kb);
            }
            #pragma unroll
            for (int nt = 0; nt < 4; ++nt)
                ldsm_x4(bh[nt], st + BHI_OFF + (brow + nt * 16) * 80 + kb);

            #pragma unroll
            for (int mt = 0; mt < 2; ++mt)
                #pragma unroll
                for (int j = 0; j < 8; ++j)
                    mma_f16(acc[mt][j], ah[mt], bh[j >> 1][j & 1],
                            bh[j >> 1][(j & 1) + 2]);
            #pragma unroll
            for (int mt = 0; mt < 2; ++mt)
                #pragma unroll
                for (int j = 0; j < 8; ++j)
                    mma_f16(acc[mt][j], al[mt], bh[j >> 1][j & 1],
                            bh[j >> 1][(j & 1) + 2]);
        }
        __syncthreads();
    }

    // epilogue
    const int g = lane >> 2, tq = lane & 3;
    #pragma unroll
    for (int mt = 0; mt < 2; ++mt) {
        const int r0 = bm + wm + mt * 16 + g;
        #pragma unroll
        for (int j = 0; j < 8; ++j) {
            const int col = bn + wn + j * 8 + tq * 2;
            const float b0 = bias[col], b1 = bias[col + 1];
            float v00 = acc[mt][j][0] + b0, v01 = acc[mt][j][1] + b1;
            float v10 = acc[mt][j][2] + b0, v11 = acc[mt][j][3] + b1;
            if (C) {
                *(float2*)&C[(size_t)r0 * Nc + col] = make_float2(v00, v01);
                *(float2*)&C[(size_t)(r0 + 8) * Nc + col] = make_float2(v10, v11);
            } else {
                split_store2(Chi, Clo, (size_t)r0 * Nc + col, v00, v01);
                split_store2(Chi, Clo, (size_t)(r0 + 8) * Nc + col, v10, v11);
            }
        }
    }
}

// ---------------------------------------------------------------------------
// MMA attention: 128 queries per CTA, 64-key tiles, max-free two-pass softmax.
// Pass A: Q-hi only QK + vectorized f16x2 exp2 (l tolerates ~1e-4).
// Pass B: full 2-term QK, fp32 exp2, P packed to fp16-hi only for PV.
// ---------------------------------------------------------------------------
#define ATT_QHI   0
#define ATT_QLO   18432
#define ATT_STG   36864
#define ATT_STAGE 18432
#define ATT_VOF   9216
#define ATT_SMEM  73728

__global__ __launch_bounds__(256, 2) void attn_mma_kernel(float* __restrict__ attn_mean)
{
    extern __shared__ char smc[];
    const uint32_t sb = smem_to_u32(smc);
    const int tid = threadIdx.x, lane = tid & 31, wid = tid >> 5;
    const int g = lane >> 2, tg = lane & 3;
    const int h = blockIdx.y >> 1, b = blockIdx.y & 1;
    const int q0 = blockIdx.x * 128;
    const float CEXP = 0.18033688f;  // 0.125 * log2(e)
    const float MSCALE = 1.0f / (NHEADS * (float)NSEQ);

    // hoisted per-thread loader bases (r, ch fixed per thread slot)
    const int lr = tid >> 3, lch = tid & 7;          // r = lr + i*32, ch = lch
    const size_t rowQ  = ((size_t)(b * NSEQ + q0 + lr)) * TD + h * 192 + lch * 8;
    const size_t rowKV = ((size_t)(b * NSEQ + lr)) * TD + h * 192 + lch * 8;
    const uint32_t soff = lr * 144 + lch * 16;
    const size_t KTSTEP = (size_t)64 * TD;

    auto loadQ = [&]() {
        #pragma unroll
        for (int i = 0; i < 4; ++i) {
            size_t go = rowQ + (size_t)i * 32 * TD;
            cp16(sb + ATT_QHI + soff + i * 32 * 144, g_qkvhi + go);
            cp16(sb + ATT_QLO + soff + i * 32 * 144, g_qkvlo + go);
        }
    };
    auto loadK = [&](int kt, int s) {
        uint32_t st = sb + ATT_STG + s * ATT_STAGE;
        size_t base = rowKV + (size_t)kt * KTSTEP + 64;
        cp16(st + soff,            g_qkvhi + base);
        cp16(st + soff + 32 * 144, g_qkvhi + base + 32 * TD);
    };
    auto loadKV = [&](int kt, int s) {
        uint32_t st = sb + ATT_STG + s * ATT_STAGE;
        size_t base = rowKV + (size_t)kt * KTSTEP + 64;
        cp16(st + soff,            g_qkvhi + base);
        cp16(st + soff + 32 * 144, g_qkvhi + base + 32 * TD);
        cp16(st + ATT_VOF + soff,            g_qkvhi + base + 64);
        cp16(st + ATT_VOF + soff + 32 * 144, g_qkvhi + base + 64 + 32 * TD);
    };

    const uint32_t klb  = (lane >> 4) * 16;
    const uint32_t arow = wid * 16 + (lane & 15);
    const uint32_t brow = lane & 15;

    auto computeS = [&](uint32_t stg, float (*acc)[4], bool full) {
        #pragma unroll
        for (int ks = 0; ks < 4; ++ks) {
            const uint32_t kb = ks * 32 + klb;
            uint32_t ah[4], bh[4][4];
            ldsm_x4(ah, sb + ATT_QHI + arow * 144 + kb);
            #pragma unroll
            for (int nt = 0; nt < 4; ++nt)
                ldsm_x4(bh[nt], stg + (brow + nt * 16) * 144 + kb);
            #pragma unroll
            for (int nt = 0; nt < 4; ++nt)
                #pragma unroll
                for (int o = 0; o < 2; ++o)
                    mma_f16(acc[nt * 2 + o], ah, bh[nt][o], bh[nt][o + 2]);
            if (full) {
                uint32_t al[4];
                ldsm_x4(al, sb + ATT_QLO + arow * 144 + kb);
                #pragma unroll
                for (int nt = 0; nt < 4; ++nt)
                    #pragma unroll
                    for (int o = 0; o < 2; ++o)
                        mma_f16(acc[nt * 2 + o], al, bh[nt][o], bh[nt][o + 2]);
            }
        }
    };

    float l0 = 0.f, l1 = 0.f;

    // ====== PASS A: sumexp only (max-free, Q-hi only, f16x2 exp) ==========
    loadQ(); loadK(0, 0); cp_commit();
    loadK(1, 1); cp_commit();

    for (int kt = 0; kt < 32; ++kt) {
        cp_wait<1>();
        __syncthreads();
        const uint32_t stg = sb + ATT_STG + (kt & 1) * ATT_STAGE;

        float acc[8][4];
        #pragma unroll
        for (int j = 0; j < 8; ++j)
            #pragma unroll
            for (int x = 0; x < 4; ++x) acc[j][x] = 0.f;
        computeS(stg, acc, false);

        #pragma unroll
        for (int j = 0; j < 8; ++j) {
            uint32_t e01 = ex2_h2(acc[j][0] * CEXP, acc[j][1] * CEXP);
            uint32_t e23 = ex2_h2(acc[j][2] * CEXP, acc[j][3] * CEXP);
            float2 f01 = __half22float2(*(__half2*)&e01);
            float2 f23 = __half22float2(*(__half2*)&e23);
            l0 += f01.x + f01.y;
            l1 += f23.x + f23.y;
        }

        __syncthreads();
        if (kt + 2 < 32) loadK(kt + 2, kt & 1);
        cp_commit();
    }

    // quad reduce (4 lanes share each row)
    l0 += __shfl_xor_sync(0xffffffffu, l0, 1);
    l0 += __shfl_xor_sync(0xffffffffu, l0, 2);
    l1 += __shfl_xor_sync(0xffffffffu, l1, 1);
    l1 += __shfl_xor_sync(0xffffffffu, l1, 2);
    const float rlog0 = -lg2(l0), rlog1 = -lg2(l1);

    float ctx[8][4];
    #pragma unroll
    for (int j = 0; j < 8; ++j)
        #pragma unroll
        for (int x = 0; x < 4; ++x) ctx[j][x] = 0.f;

    // ================= PASS B =================
    loadKV(0, 0); cp_commit();
    loadKV(1, 1); cp_commit();

    for (int kt = 0; kt < 32; ++kt) {
        cp_wait<1>();
        __syncthreads();
        const uint32_t stg = sb + ATT_STG + (kt & 1) * ATT_STAGE;

        float acc[8][4];
        #pragma unroll
        for (int j = 0; j < 8; ++j)
            #pragma unroll
            for (int x = 0; x < 4; ++x) acc[j][x] = 0.f;
        computeS(stg, acc, true);

        float* amrow = &attn_mean[b * NSEQ + kt * 64];

        // per 16-col block: fp32 exp, pack P-hi, column sums, P@V (hi only)
        #pragma unroll
        for (int kc = 0; kc < 4; ++kc) {
            const int j0 = kc * 2, j1 = j0 + 1;
            float p00 = ex2(fmaf(acc[j0][0], CEXP, rlog0));
            float p01 = ex2(fmaf(acc[j0][1], CEXP, rlog0));
            float p02 = ex2(fmaf(acc[j0][2], CEXP, rlog1));
            float p03 = ex2(fmaf(acc[j0][3], CEXP, rlog1));
            float p10 = ex2(fmaf(acc[j1][0], CEXP, rlog0));
            float p11 = ex2(fmaf(acc[j1][1], CEXP, rlog0));
            float p12 = ex2(fmaf(acc[j1][2], CEXP, rlog1));
            float p13 = ex2(fmaf(acc[j1][3], CEXP, rlog1));

            uint32_t aph[4];
            aph[0] = pack_h2(p00, p01);
            aph[1] = pack_h2(p02, p03);
            aph[2] = pack_h2(p10, p11);
            aph[3] = pack_h2(p12, p13);

            // column partial sums (rows g + g+8), quad-spread reduce
            float cA0 = p00 + p02, cA1 = p01 + p03;
            float cB0 = p10 + p12, cB1 = p11 + p13;
            cA0 += __shfl_xor_sync(0xffffffffu, cA0, 4);
            cA0 += __shfl_xor_sync(0xffffffffu, cA0, 8);
            cA0 += __shfl_xor_sync(0xffffffffu, cA0, 16);
            cA1 += __shfl_xor_sync(0xffffffffu, cA1, 4);
            cA1 += __shfl_xor_sync(0xffffffffu, cA1, 8);
            cA1 += __shfl_xor_sync(0xffffffffu, cA1, 16);
            cB0 += __shfl_xor_sync(0xffffffffu, cB0, 4);
            cB0 += __shfl_xor_sync(0xffffffffu, cB0, 8);
            cB0 += __shfl_xor_sync(0xffffffffu, cB0, 16);
            cB1 += __shfl_xor_sync(0xffffffffu, cB1, 4);
            cB1 += __shfl_xor_sync(0xffffffffu, cB1, 8);
            cB1 += __shfl_xor_sync(0xffffffffu, cB1, 16);
            if (lane < 4) {
                atomicAdd(&amrow[j0 * 8 + lane * 2],     cA0 * MSCALE);
                atomicAdd(&amrow[j0 * 8 + lane * 2 + 1], cA1 * MSCALE);
                atomicAdd(&amrow[j1 * 8 + lane * 2],     cB0 * MSCALE);
                atomicAdd(&amrow[j1 * 8 + lane * 2 + 1], cB1 * MSCALE);
            }

            // P @ V: P hi only, V hi only
            #pragma unroll
            for (int dkt = 0; dkt < 4; ++dkt) {
                const uint32_t off = (kc * 16 + (lane & 15)) * 144 + dkt * 32
                                   + (lane >> 4) * 16;
                uint32_t vh[4];
                ldsm_x4_t(vh, stg + ATT_VOF + off);
                mma_f16(ctx[dkt * 2],     aph, vh[0], vh[1]);
                mma_f16(ctx[dkt * 2 + 1], aph, vh[2], vh[3]);
            }
        }

        __syncthreads();
        if (kt + 2 < 32) loadKV(kt + 2, kt & 1);
        cp_commit();
    }

    // epilogue: write context hi/lo fp16 (B, N, H*dk layout)
    const int r0 = q0 + wid * 16 + g;
    #pragma unroll
    for (int nd = 0; nd < 8; ++nd) {
        const int col = h * 64 + nd * 8 + tg * 2;
        size_t i0 = ((size_t)(b * NSEQ + r0)) * DMODEL + col;
        split_store2(g_ctxhi, g_ctxlo, i0, ctx[nd][0], ctx[nd][1]);
        split_store2(g_ctxhi, g_ctxlo, i0 + 8 * DMODEL, ctx[nd][2], ctx[nd][3]);
    }
}

// ---------------------------------------------------------------------------
extern "C" void kernel_launch(void* const* d_in, const int* in_sizes, int n_in,
                              void* d_out, int out_size)
{
    const float* x     = (const float*)d_in[0];
    const float* w_qkv = (const float*)d_in[1];
    const float* b_qkv = (const float*)d_in[2];
    const float* w_out = (const float*)d_in[3];
    const float* b_out = (const float*)d_in[4];
    float* out = (float*)d_out;

    __half *qh, *ql, *xhi, *xlo, *ctxhi, *ctxlo, *wqh, *woh;
    cudaGetSymbolAddress((void**)&qh, g_qkvhi);
    cudaGetSymbolAddress((void**)&ql, g_qkvlo);
    cudaGetSymbolAddress((void**)&xhi, g_xhi);
    cudaGetSymbolAddress((void**)&xlo, g_xlo);
    cudaGetSymbolAddress((void**)&ctxhi, g_ctxhi);
    cudaGetSymbolAddress((void**)&ctxlo, g_ctxlo);
    cudaGetSymbolAddress((void**)&wqh, g_wqkvT_h);
    cudaGetSymbolAddress((void**)&woh, g_woutT_h);

    const int M = BDIM * NSEQ;                    // 4096
    float* attn_mean = out + (size_t)M * DMODEL;  // second output region

    cudaMemsetAsync(attn_mean, 0, (size_t)BDIM * NSEQ * sizeof(float));

    // prep: split input, cast+transpose weights (hi only)
    split_kernel<<<1024, 256>>>(x, xhi, xlo, M * DMODEL / 2);
    transpose_h_kernel<<<dim3(TD / 32, DMODEL / 32), dim3(32, 8)>>>(
        w_qkv, wqh, DMODEL, TD);
    transpose_h_kernel<<<dim3(DMODEL / 32, DMODEL / 32), dim3(32, 8)>>>(
        w_out, woh, DMODEL, DMODEL);

    cudaFuncSetAttribute(gemm_mma_kernel,
                         cudaFuncAttributeMaxDynamicSharedMemorySize,
                         (int)GEMM_SMEM);
    cudaFuncSetAttribute(attn_mma_kernel,
                         cudaFuncAttributeMaxDynamicSharedMemorySize,
                         ATT_SMEM);

    // QKV projection -> split fp16 output
    gemm_mma_kernel<<<dim3(TD / 128, M / 128), 256, GEMM_SMEM>>>(
        xhi, xlo, wqh, b_qkv, nullptr, qh, ql, M, TD, DMODEL);

    // attention (mma, max-free two-pass)
    attn_mma_kernel<<<dim3(NSEQ / 128, NHEADS * BDIM), 256, ATT_SMEM>>>(attn_mean);

    // output projection -> fp32 final output
    gemm_mma_kernel<<<dim3(DMODEL / 128, M / 128), 256, GEMM_SMEM>>>(
        ctxhi, ctxlo, woh, b_out, out, nullptr, nullptr, M, DMODEL, DMODEL);
}

// round 9
// speedup vs baseline: 5.1231x; 1.0711x over previous
#include <cuda_runtime.h>
#include <cuda_fp16.h>
#include <cstdint>

#define BDIM   2
#define NSEQ   2048
#define DMODEL 1024
#define NHEADS 16
#define DKH    64
#define TD     3072   // 3*DMODEL

// ---------------------------------------------------------------------------
// Scratch (static device globals: allocation-free rule)
// ---------------------------------------------------------------------------
__device__ __half g_qkvhi[(size_t)BDIM * NSEQ * TD];
__device__ __half g_xhi[(size_t)BDIM * NSEQ * DMODEL];
__device__ __half g_xlo[(size_t)BDIM * NSEQ * DMODEL];
__device__ __half g_ctxhi[(size_t)BDIM * NSEQ * DMODEL];
__device__ __half g_ctxlo[(size_t)BDIM * NSEQ * DMODEL];
__device__ __half g_wqkvT_h[(size_t)TD * DMODEL];   // [N=3072][K=1024] hi only
__device__ __half g_woutT_h[(size_t)DMODEL * DMODEL];

// ---------------------------------------------------------------------------
// PTX helpers (baseline ISA only: compiles under compute_103)
// ---------------------------------------------------------------------------
__device__ __forceinline__ uint32_t smem_to_u32(const void* p) {
    uint32_t a;
    asm("{ .reg .u64 t; cvta.to.shared.u64 t, %1; cvt.u32.u64 %0, t; }"
        : "=r"(a) : "l"(p));
    return a;
}
__device__ __forceinline__ void cp16(uint32_t s, const void* g) {
    asm volatile("cp.async.ca.shared.global [%0], [%1], 16;" :: "r"(s), "l"(g));
}
__device__ __forceinline__ void cp_commit() {
    asm volatile("cp.async.commit_group;");
}
template <int N> __device__ __forceinline__ void cp_wait() {
    asm volatile("cp.async.wait_group %0;" :: "n"(N));
}
__device__ __forceinline__ void ldsm_x4(uint32_t* r, uint32_t addr) {
    asm volatile("ldmatrix.sync.aligned.m8n8.x4.shared.b16 {%0,%1,%2,%3}, [%4];"
        : "=r"(r[0]), "=r"(r[1]), "=r"(r[2]), "=r"(r[3]) : "r"(addr));
}
__device__ __forceinline__ void ldsm_x4_t(uint32_t* r, uint32_t addr) {
    asm volatile("ldmatrix.sync.aligned.m8n8.x4.trans.shared.b16 {%0,%1,%2,%3}, [%4];"
        : "=r"(r[0]), "=r"(r[1]), "=r"(r[2]), "=r"(r[3]) : "r"(addr));
}
__device__ __forceinline__ void mma_f16(float* d, const uint32_t* a,
                                        uint32_t b0, uint32_t b1) {
    asm volatile(
        "mma.sync.aligned.m16n8k16.row.col.f32.f16.f16.f32 "
        "{%0,%1,%2,%3}, {%4,%5,%6,%7}, {%8,%9}, {%0,%1,%2,%3};"
        : "+f"(d[0]), "+f"(d[1]), "+f"(d[2]), "+f"(d[3])
        : "r"(a[0]), "r"(a[1]), "r"(a[2]), "r"(a[3]), "r"(b0), "r"(b1));
}
__device__ __forceinline__ float ex2(float x) {
    float y; asm("ex2.approx.f32 %0, %1;" : "=f"(y) : "f"(x)); return y;
}
__device__ __forceinline__ float lg2(float x) {
    float y; asm("lg2.approx.f32 %0, %1;" : "=f"(y) : "f"(x)); return y;
}
// pack (lo, hi) floats into one f16x2 register
__device__ __forceinline__ uint32_t pack_h2(float lo, float hi) {
    uint32_t p;
    asm("cvt.rn.f16x2.f32 %0, %1, %2;" : "=r"(p) : "f"(hi), "f"(lo));
    return p;
}
// vectorized exp2: returns f16x2{exp2(lo), exp2(hi)}
__device__ __forceinline__ uint32_t ex2_h2(float lo, float hi) {
    uint32_t p, r;
    asm("cvt.rn.f16x2.f32 %0, %1, %2;" : "=r"(p) : "f"(hi), "f"(lo));
    asm("ex2.approx.f16x2 %0, %1;" : "=r"(r) : "r"(p));
    return r;
}
__device__ __forceinline__ void pack_hl(float x, float y,
                                        uint32_t& hp, uint32_t& lp) {
    __half2 hh = __floats2half2_rn(x, y);
    __half2 ll = __floats2half2_rn(x - __half2float(__low2half(hh)),
                                   y - __half2float(__high2half(hh)));
    hp = *(uint32_t*)&hh; lp = *(uint32_t*)&ll;
}
__device__ __forceinline__ void split_store2(__half* hi, __half* lo,
                                             size_t idx, float x, float y) {
    uint32_t hp, lp;
    pack_hl(x, y, hp, lp);
    *(uint32_t*)(hi + idx) = hp;
    *(uint32_t*)(lo + idx) = lp;
}

// ---------------------------------------------------------------------------
// Split fp32 -> (hi, lo) fp16, elementwise
// ---------------------------------------------------------------------------
__global__ __launch_bounds__(256) void split_kernel(
    const float* __restrict__ src, __half* __restrict__ hi,
    __half* __restrict__ lo, int n2)
{
    for (int i = blockIdx.x * blockDim.x + threadIdx.x; i < n2;
         i += gridDim.x * blockDim.x) {
        float2 v = ((const float2*)src)[i];
        split_store2(hi, lo, (size_t)i * 2, v.x, v.y);
    }
}

// ---------------------------------------------------------------------------
// Transpose + fp16 cast: src [K][N] fp32 -> hiT [N][K] fp16 (hi only)
// ---------------------------------------------------------------------------
__global__ __launch_bounds__(256) void transpose_h_kernel(
    const float* __restrict__ src, __half* __restrict__ hiT, int K, int N)
{
    __shared__ float tile[32][33];
    const int tx = threadIdx.x, ty = threadIdx.y;   // (32, 8)
    const int n0 = blockIdx.x * 32, k0 = blockIdx.y * 32;

    #pragma unroll
    for (int i = 0; i < 4; ++i)
        tile[ty + i * 8][tx] = src[(size_t)(k0 + ty + i * 8) * N + n0 + tx];
    __syncthreads();

    #pragma unroll
    for (int i = 0; i < 4; ++i) {
        int n = n0 + ty + i * 8;
        hiT[(size_t)n * K + k0 + tx] = __float2half_rn(tile[tx][ty + i * 8]);
    }
}

// ---------------------------------------------------------------------------
// fp16 2-term split GEMM: C = A @ B + bias
// A = hi/lo fp16 [M][K]; B = hi fp16 transposed [Nc][K].
// Output: fp32 C, or split (Chi, Clo), or hi-only Chi.
// CTA 128x128, BK=32, 256 threads, warp tile 32x64, cp.async 2-stage.
// ---------------------------------------------------------------------------
#define AHI_OFF 0
#define ALO_OFF 10240
#define BHI_OFF 20480
#define STAGE_SZ 30720
static constexpr size_t GEMM_SMEM = 2 * STAGE_SZ;  // 61440

__global__ __launch_bounds__(256, 2) void gemm_mma_kernel(
    const __half* __restrict__ Ahi, const __half* __restrict__ Alo,
    const __half* __restrict__ BTh,
    const float* __restrict__ bias, float* __restrict__ C,
    __half* __restrict__ Chi, __half* __restrict__ Clo,
    int M, int Nc, int K)
{
    extern __shared__ char smc[];
    const uint32_t sbase = smem_to_u32(smc);
    const int tid = threadIdx.x;
    const int lane = tid & 31, wid = tid >> 5;
    const int wm = (wid & 3) * 32;
    const int wn = (wid >> 2) * 64;
    const int bm = blockIdx.y * 128, bn = blockIdx.x * 128;

    const int lrow = tid >> 1;
    const int lc   = (tid & 1) * 2;

    const __half* gAh = Ahi + (size_t)(bm + lrow) * K + lc * 8;
    const __half* gAl = Alo + (size_t)(bm + lrow) * K + lc * 8;
    const __half* gBh = BTh + (size_t)(bn + lrow) * K + lc * 8;

    const uint32_t sRow = lrow * 80 + lc * 16;

    auto load_stage = [&](int k0, int buf) {
        uint32_t st = sbase + buf * STAGE_SZ;
        cp16(st + AHI_OFF + sRow,      gAh + k0);
        cp16(st + AHI_OFF + sRow + 16, gAh + k0 + 8);
        cp16(st + ALO_OFF + sRow,      gAl + k0);
        cp16(st + ALO_OFF + sRow + 16, gAl + k0 + 8);
        cp16(st + BHI_OFF + sRow,      gBh + k0);
        cp16(st + BHI_OFF + sRow + 16, gBh + k0 + 8);
    };

    float acc[2][8][4];
    #pragma unroll
    for (int a = 0; a < 2; ++a)
        #pragma unroll
        for (int b = 0; b < 8; ++b)
            #pragma unroll
            for (int c = 0; c < 4; ++c) acc[a][b][c] = 0.f;

    const int arow = wm + (lane & 15);
    const int brow = wn + (lane & 15);
    const int klb  = (lane >> 4) * 16;

    const int nit = K / 32;
    load_stage(0, 0);
    cp_commit();

    for (int i = 0; i < nit; ++i) {
        const int cur = i & 1;
        if (i + 1 < nit) { load_stage((i + 1) * 32, cur ^ 1); cp_commit(); }
        if (i + 1 < nit) cp_wait<1>(); else cp_wait<0>();
        __syncthreads();

        const uint32_t st = sbase + cur * STAGE_SZ;
        #pragma unroll
        for (int ks = 0; ks < 2; ++ks) {
            const uint32_t kb = ks * 32 + klb;
            uint32_t ah[2][4], al[2][4], bh[4][4];
            #pragma unroll
            for (int mt = 0; mt < 2; ++mt) {
                ldsm_x4(ah[mt], st + AHI_OFF + (arow + mt * 16) * 80 + kb);
                ldsm_x4(al[mt], st + ALO_OFF + (arow + mt * 16) * 80 + kb);
            }
            #pragma unroll
            for (int nt = 0; nt < 4; ++nt)
                ldsm_x4(bh[nt], st + BHI_OFF + (brow + nt * 16) * 80 + kb);

            #pragma unroll
            for (int mt = 0; mt < 2; ++mt)
                #pragma unroll
                for (int j = 0; j < 8; ++j)
                    mma_f16(acc[mt][j], ah[mt], bh[j >> 1][j & 1],
                            bh[j >> 1][(j & 1) + 2]);
            #pragma unroll
            for (int mt = 0; mt < 2; ++mt)
                #pragma unroll
                for (int j = 0; j < 8; ++j)
                    mma_f16(acc[mt][j], al[mt], bh[j >> 1][j & 1],
                            bh[j >> 1][(j & 1) + 2]);
        }
        __syncthreads();
    }

    // epilogue
    const int g = lane >> 2, tq = lane & 3;
    #pragma unroll
    for (int mt = 0; mt < 2; ++mt) {
        const int r0 = bm + wm + mt * 16 + g;
        #pragma unroll
        for (int j = 0; j < 8; ++j) {
            const int col = bn + wn + j * 8 + tq * 2;
            const float b0 = bias[col], b1 = bias[col + 1];
            float v00 = acc[mt][j][0] + b0, v01 = acc[mt][j][1] + b1;
            float v10 = acc[mt][j][2] + b0, v11 = acc[mt][j][3] + b1;
            if (C) {
                *(float2*)&C[(size_t)r0 * Nc + col] = make_float2(v00, v01);
                *(float2*)&C[(size_t)(r0 + 8) * Nc + col] = make_float2(v10, v11);
            } else if (Clo) {
                split_store2(Chi, Clo, (size_t)r0 * Nc + col, v00, v01);
                split_store2(Chi, Clo, (size_t)(r0 + 8) * Nc + col, v10, v11);
            } else {
                *(uint32_t*)(Chi + (size_t)r0 * Nc + col) = pack_h2(v00, v01);
                *(uint32_t*)(Chi + (size_t)(r0 + 8) * Nc + col) = pack_h2(v10, v11);
            }
        }
    }
}

// ---------------------------------------------------------------------------
// MMA attention, deferred-normalization single-compute design:
// Pass 1: S = QK (hi only), e = fp32 exp2 (unnormalized), l += e,
//         ctxU += e*V (fp16 P-hi, fp32 accum). No shuffles in loop.
// Pass 2: recompute S (hi only), f16x2 exp with final normalizer, column sums
//         via shfl + atomics.
// Epilogue: ctx = ctxU / l, split-store.
// ---------------------------------------------------------------------------
#define ATT_QHI   0
#define ATT_STG   18432
#define ATT_STAGE 18432
#define ATT_VOF   9216
#define ATT_SMEM  55296

__global__ __launch_bounds__(256, 2) void attn_mma_kernel(float* __restrict__ attn_mean)
{
    extern __shared__ char smc[];
    const uint32_t sb = smem_to_u32(smc);
    const int tid = threadIdx.x, lane = tid & 31, wid = tid >> 5;
    const int g = lane >> 2, tg = lane & 3;
    const int h = blockIdx.y >> 1, b = blockIdx.y & 1;
    const int q0 = blockIdx.x * 128;
    const float CEXP = 0.18033688f;  // 0.125 * log2(e)
    const float MSCALE = 1.0f / (NHEADS * (float)NSEQ);

    // hoisted per-thread loader bases
    const int lr = tid >> 3, lch = tid & 7;
    const size_t rowQ  = ((size_t)(b * NSEQ + q0 + lr)) * TD + h * 192 + lch * 8;
    const size_t rowKV = ((size_t)(b * NSEQ + lr)) * TD + h * 192 + lch * 8;
    const uint32_t soff = lr * 144 + lch * 16;
    const size_t KTSTEP = (size_t)64 * TD;

    auto loadQ = [&]() {
        #pragma unroll
        for (int i = 0; i < 4; ++i)
            cp16(sb + ATT_QHI + soff + i * 32 * 144,
                 g_qkvhi + rowQ + (size_t)i * 32 * TD);
    };
    auto loadK = [&](int kt, int s) {
        uint32_t st = sb + ATT_STG + s * ATT_STAGE;
        size_t base = rowKV + (size_t)kt * KTSTEP + 64;
        cp16(st + soff,            g_qkvhi + base);
        cp16(st + soff + 32 * 144, g_qkvhi + base + 32 * TD);
    };
    auto loadKV = [&](int kt, int s) {
        uint32_t st = sb + ATT_STG + s * ATT_STAGE;
        size_t base = rowKV + (size_t)kt * KTSTEP + 64;
        cp16(st + soff,            g_qkvhi + base);
        cp16(st + soff + 32 * 144, g_qkvhi + base + 32 * TD);
        cp16(st + ATT_VOF + soff,            g_qkvhi + base + 64);
        cp16(st + ATT_VOF + soff + 32 * 144, g_qkvhi + base + 64 + 32 * TD);
    };

    const uint32_t klb  = (lane >> 4) * 16;
    const uint32_t arow = wid * 16 + (lane & 15);
    const uint32_t brow = lane & 15;

    auto computeS = [&](uint32_t stg, float (*acc)[4]) {
        #pragma unroll
        for (int ks = 0; ks < 4; ++ks) {
            const uint32_t kb = ks * 32 + klb;
            uint32_t ah[4], bh[4][4];
            ldsm_x4(ah, sb + ATT_QHI + arow * 144 + kb);
            #pragma unroll
            for (int nt = 0; nt < 4; ++nt)
                ldsm_x4(bh[nt], stg + (brow + nt * 16) * 144 + kb);
            #pragma unroll
            for (int nt = 0; nt < 4; ++nt)
                #pragma unroll
                for (int o = 0; o < 2; ++o)
                    mma_f16(acc[nt * 2 + o], ah, bh[nt][o], bh[nt][o + 2]);
        }
    };

    float l0 = 0.f, l1 = 0.f;
    float ctx[8][4];
    #pragma unroll
    for (int j = 0; j < 8; ++j)
        #pragma unroll
        for (int x = 0; x < 4; ++x) ctx[j][x] = 0.f;

    // ====== PASS 1: unnormalized e, l accumulation, ctxU += e*V ===========
    loadQ(); loadKV(0, 0); cp_commit();
    loadKV(1, 1); cp_commit();

    for (int kt = 0; kt < 32; ++kt) {
        cp_wait<1>();
        __syncthreads();
        const uint32_t stg = sb + ATT_STG + (kt & 1) * ATT_STAGE;

        float acc[8][4];
        #pragma unroll
        for (int j = 0; j < 8; ++j)
            #pragma unroll
            for (int x = 0; x < 4; ++x) acc[j][x] = 0.f;
        computeS(stg, acc);

        #pragma unroll
        for (int kc = 0; kc < 4; ++kc) {
            const int j0 = kc * 2, j1 = j0 + 1;
            float e00 = ex2(acc[j0][0] * CEXP);
            float e01 = ex2(acc[j0][1] * CEXP);
            float e02 = ex2(acc[j0][2] * CEXP);
            float e03 = ex2(acc[j0][3] * CEXP);
            float e10 = ex2(acc[j1][0] * CEXP);
            float e11 = ex2(acc[j1][1] * CEXP);
            float e12 = ex2(acc[j1][2] * CEXP);
            float e13 = ex2(acc[j1][3] * CEXP);
            l0 += e00 + e01 + e10 + e11;
            l1 += e02 + e03 + e12 + e13;

            uint32_t aph[4];
            aph[0] = pack_h2(e00, e01);
            aph[1] = pack_h2(e02, e03);
            aph[2] = pack_h2(e10, e11);
            aph[3] = pack_h2(e12, e13);

            #pragma unroll
            for (int dkt = 0; dkt < 4; ++dkt) {
                const uint32_t off = (kc * 16 + (lane & 15)) * 144 + dkt * 32
                                   + (lane >> 4) * 16;
                uint32_t vh[4];
                ldsm_x4_t(vh, stg + ATT_VOF + off);
                mma_f16(ctx[dkt * 2],     aph, vh[0], vh[1]);
                mma_f16(ctx[dkt * 2 + 1], aph, vh[2], vh[3]);
            }
        }

        __syncthreads();
        if (kt + 2 < 32) loadKV(kt + 2, kt & 1);
        cp_commit();
    }

    // quad reduce l (4 lanes share each row)
    l0 += __shfl_xor_sync(0xffffffffu, l0, 1);
    l0 += __shfl_xor_sync(0xffffffffu, l0, 2);
    l1 += __shfl_xor_sync(0xffffffffu, l1, 1);
    l1 += __shfl_xor_sync(0xffffffffu, l1, 2);
    const float rlog0 = -lg2(l0), rlog1 = -lg2(l1);
    const float rinv0 = 1.0f / l0, rinv1 = 1.0f / l1;

    // ====== PASS 2: column sums with final normalizer =====================
    loadK(0, 0); cp_commit();
    loadK(1, 1); cp_commit();

    for (int kt = 0; kt < 32; ++kt) {
        cp_wait<1>();
        __syncthreads();
        const uint32_t stg = sb + ATT_STG + (kt & 1) * ATT_STAGE;

        float acc[8][4];
        #pragma unroll
        for (int j = 0; j < 8; ++j)
            #pragma unroll
            for (int x = 0; x < 4; ++x) acc[j][x] = 0.f;
        computeS(stg, acc);

        float* amrow = &attn_mean[b * NSEQ + kt * 64];
        #pragma unroll
        for (int j = 0; j < 8; ++j) {
            uint32_t e01 = ex2_h2(fmaf(acc[j][0], CEXP, rlog0),
                                  fmaf(acc[j][1], CEXP, rlog0));
            uint32_t e23 = ex2_h2(fmaf(acc[j][2], CEXP, rlog1),
                                  fmaf(acc[j][3], CEXP, rlog1));
            float2 f01 = __half22float2(*(__half2*)&e01);
            float2 f23 = __half22float2(*(__half2*)&e23);
            float c0 = f01.x + f23.x, c1 = f01.y + f23.y;
            c0 += __shfl_xor_sync(0xffffffffu, c0, 4);
            c0 += __shfl_xor_sync(0xffffffffu, c0, 8);
            c0 += __shfl_xor_sync(0xffffffffu, c0, 16);
            c1 += __shfl_xor_sync(0xffffffffu, c1, 4);
            c1 += __shfl_xor_sync(0xffffffffu, c1, 8);
            c1 += __shfl_xor_sync(0xffffffffu, c1, 16);
            if (lane < 4) {
                atomicAdd(&amrow[j * 8 + lane * 2],     c0 * MSCALE);
                atomicAdd(&amrow[j * 8 + lane * 2 + 1], c1 * MSCALE);
            }
        }

        __syncthreads();
        if (kt + 2 < 32) loadK(kt + 2, kt & 1);
        cp_commit();
    }

    // epilogue: normalize ctx, write hi/lo fp16 (B, N, H*dk layout)
    const int r0 = q0 + wid * 16 + g;
    #pragma unroll
    for (int nd = 0; nd < 8; ++nd) {
        const int col = h * 64 + nd * 8 + tg * 2;
        size_t i0 = ((size_t)(b * NSEQ + r0)) * DMODEL + col;
        split_store2(g_ctxhi, g_ctxlo, i0,
                     ctx[nd][0] * rinv0, ctx[nd][1] * rinv0);
        split_store2(g_ctxhi, g_ctxlo, i0 + 8 * DMODEL,
                     ctx[nd][2] * rinv1, ctx[nd][3] * rinv1);
    }
}

// ---------------------------------------------------------------------------
extern "C" void kernel_launch(void* const* d_in, const int* in_sizes, int n_in,
                              void* d_out, int out_size)
{
    const float* x     = (const float*)d_in[0];
    const float* w_qkv = (const float*)d_in[1];
    const float* b_qkv = (const float*)d_in[2];
    const float* w_out = (const float*)d_in[3];
    const float* b_out = (const float*)d_in[4];
    float* out = (float*)d_out;

    __half *qh, *xhi, *xlo, *ctxhi, *ctxlo, *wqh, *woh;
    cudaGetSymbolAddress((void**)&qh, g_qkvhi);
    cudaGetSymbolAddress((void**)&xhi, g_xhi);
    cudaGetSymbolAddress((void**)&xlo, g_xlo);
    cudaGetSymbolAddress((void**)&ctxhi, g_ctxhi);
    cudaGetSymbolAddress((void**)&ctxlo, g_ctxlo);
    cudaGetSymbolAddress((void**)&wqh, g_wqkvT_h);
    cudaGetSymbolAddress((void**)&woh, g_woutT_h);

    const int M = BDIM * NSEQ;                    // 4096
    float* attn_mean = out + (size_t)M * DMODEL;  // second output region

    cudaMemsetAsync(attn_mean, 0, (size_t)BDIM * NSEQ * sizeof(float));

    // prep: split input, cast+transpose weights (hi only)
    split_kernel<<<1024, 256>>>(x, xhi, xlo, M * DMODEL / 2);
    transpose_h_kernel<<<dim3(TD / 32, DMODEL / 32), dim3(32, 8)>>>(
        w_qkv, wqh, DMODEL, TD);
    transpose_h_kernel<<<dim3(DMODEL / 32, DMODEL / 32), dim3(32, 8)>>>(
        w_out, woh, DMODEL, DMODEL);

    cudaFuncSetAttribute(gemm_mma_kernel,
                         cudaFuncAttributeMaxDynamicSharedMemorySize,
                         (int)GEMM_SMEM);
    cudaFuncSetAttribute(attn_mma_kernel,
                         cudaFuncAttributeMaxDynamicSharedMemorySize,
                         ATT_SMEM);

    // QKV projection -> fp16 hi-only output
    gemm_mma_kernel<<<dim3(TD / 128, M / 128), 256, GEMM_SMEM>>>(
        xhi, xlo, wqh, b_qkv, nullptr, qh, nullptr, M, TD, DMODEL);

    // attention (single-compute + colsum pass)
    attn_mma_kernel<<<dim3(NSEQ / 128, NHEADS * BDIM), 256, ATT_SMEM>>>(attn_mean);

    // output projection -> fp32 final output
    gemm_mma_kernel<<<dim3(DMODEL / 128, M / 128), 256, GEMM_SMEM>>>(
        ctxhi, ctxlo, woh, b_out, out, nullptr, nullptr, M, DMODEL, DMODEL);
}